// round 3
// baseline (speedup 1.0000x reference)
#include <cuda_runtime.h>

#define N_NODES 50000
#define N_EDGES 800000
#define HD_SCALE 0.17677669529663687f   // 1/sqrt(32)

// ---------------- scratch (device globals: no allocation allowed) ----------
__device__ __align__(256) float g_Q[N_NODES * 128];
__device__ __align__(256) float g_K[N_NODES * 128];
__device__ __align__(256) float g_V[N_NODES * 128];
__device__ __align__(256) float g_attn[N_EDGES * 4];   // stores exp(logit)
__device__ __align__(256) float g_sum[N_NODES * 4];
__device__ __align__(256) float g_agg[N_NODES * 128];
__device__ __align__(256) float g_Wf[128 * 128];
__device__ __align__(256) float g_bf[128];

// ---------------- packed f32x2 helpers --------------------------------------
__device__ __forceinline__ unsigned long long pack2(float lo, float hi) {
    unsigned long long r;
    asm("mov.b64 %0, {%1, %2};" : "=l"(r) : "f"(lo), "f"(hi));
    return r;
}
__device__ __forceinline__ unsigned long long dup2(float v) {
    unsigned long long r;
    asm("mov.b64 %0, {%1, %1};" : "=l"(r) : "f"(v));
    return r;
}
__device__ __forceinline__ void fma2(unsigned long long& d, unsigned long long a,
                                     unsigned long long b) {
    asm("fma.rn.f32x2 %0, %1, %2, %0;" : "+l"(d) : "l"(a), "l"(b));
}
__device__ __forceinline__ void unpack2(unsigned long long v, float& lo, float& hi) {
    asm("mov.b64 {%0, %1}, %2;" : "=f"(lo), "=f"(hi) : "l"(v));
}

// ---------------- init: zero accumulators -----------------------------------
__global__ void k_init() {
    int i = blockIdx.x * 256 + threadIdx.x;
    float4 z = make_float4(0.f, 0.f, 0.f, 0.f);
    if (i < N_NODES * 32) ((float4*)g_agg)[i] = z;
    if (i < N_NODES) ((float4*)g_sum)[i] = z;
}

// ---------------- fuse Wo into Wm lower half --------------------------------
__global__ void k_fusew(const float* __restrict__ Wo, const float* __restrict__ Wm,
                        const float* __restrict__ bo, const float* __restrict__ bm) {
    int r = blockIdx.x;        // 0..127
    int j = threadIdx.x;       // 0..127
    float acc = 0.f;
    #pragma unroll 8
    for (int k = 0; k < 128; k++)
        acc += Wo[r * 128 + k] * Wm[(128 + k) * 128 + j];
    g_Wf[r * 128 + j] = acc;
    if (r == 0) {
        float b = bm[j];
        #pragma unroll 8
        for (int k = 0; k < 128; k++)
            b += bo[k] * Wm[(128 + k) * 128 + j];
        g_bf[j] = b;
    }
}

// ---------------- QKV GEMM: [N,128] @ [128,128] x3, packed f32x2 ------------
__global__ __launch_bounds__(256) void k_qkv(const float* __restrict__ x,
                                             const float* __restrict__ Wq,
                                             const float* __restrict__ Wk,
                                             const float* __restrict__ Wv) {
    const float* W;
    float* out;
    if (blockIdx.y == 0)      { W = Wq; out = g_Q; }
    else if (blockIdx.y == 1) { W = Wk; out = g_K; }
    else                      { W = Wv; out = g_V; }

    int rg = threadIdx.x >> 4;                 // 0..15
    int c0 = (threadIdx.x & 15) * 8;           // 0..120
    int r0 = blockIdx.x * 64 + rg * 4;

    int rr[4];
    #pragma unroll
    for (int r = 0; r < 4; r++) {
        int ri = r0 + r;
        rr[r] = ri < N_NODES ? ri : (N_NODES - 1);
    }

    unsigned long long acc[4][4];
    #pragma unroll
    for (int r = 0; r < 4; r++)
        #pragma unroll
        for (int c = 0; c < 4; c++) acc[r][c] = 0ull;

    #pragma unroll 4
    for (int k = 0; k < 128; k++) {
        float4 w0 = *(const float4*)(W + k * 128 + c0);
        float4 w1 = *(const float4*)(W + k * 128 + c0 + 4);
        unsigned long long wp0 = pack2(w0.x, w0.y);
        unsigned long long wp1 = pack2(w0.z, w0.w);
        unsigned long long wp2 = pack2(w1.x, w1.y);
        unsigned long long wp3 = pack2(w1.z, w1.w);
        #pragma unroll
        for (int r = 0; r < 4; r++) {
            unsigned long long xp = dup2(x[(size_t)rr[r] * 128 + k]);
            fma2(acc[r][0], xp, wp0);
            fma2(acc[r][1], xp, wp1);
            fma2(acc[r][2], xp, wp2);
            fma2(acc[r][3], xp, wp3);
        }
    }

    #pragma unroll
    for (int r = 0; r < 4; r++) {
        if (r0 + r < N_NODES) {
            float o[8];
            #pragma unroll
            for (int c = 0; c < 4; c++) unpack2(acc[r][c], o[c * 2], o[c * 2 + 1]);
            float4* p = (float4*)(out + (size_t)(r0 + r) * 128 + c0);
            p[0] = make_float4(o[0], o[1], o[2], o[3]);
            p[1] = make_float4(o[4], o[5], o[6], o[7]);
        }
    }
}

// ---------------- attention: warp/edge, coalesced rows, exp, segsum ---------
__global__ __launch_bounds__(256) void k_attn(const int* __restrict__ ei,
                                              const float* __restrict__ ea,
                                              const float* __restrict__ We) {
    int e = blockIdx.x * 8 + (threadIdx.x >> 5);
    if (e >= N_EDGES) return;
    int lane = threadIdx.x & 31;
    int src = ei[e];
    int dst = ei[N_EDGES + e];

    float4 q = ((const float4*)(g_Q + (size_t)dst * 128))[lane];
    float4 k = ((const float4*)(g_K + (size_t)src * 128))[lane];
    float p = q.x * k.x + q.y * k.y + q.z * k.z + q.w * k.w;
    // reduce within 8-lane head groups
    p += __shfl_xor_sync(0xffffffffu, p, 1);
    p += __shfl_xor_sync(0xffffffffu, p, 2);
    p += __shfl_xor_sync(0xffffffffu, p, 4);

    if ((lane & 7) == 0) {
        int h = lane >> 3;
        float b = ea[e * 3 + 0] * We[0 * 4 + h]
                + ea[e * 3 + 1] * We[1 * 4 + h]
                + ea[e * 3 + 2] * We[2 * 4 + h];
        float a = p * HD_SCALE + b;
        a = a >= 0.f ? a : 0.2f * a;        // leaky_relu(0.2)
        // logits are O(7) max: exp without a stabilizer is safe in fp32, and
        // the stabilizer cancels exactly in the per-(dst,h) normalization.
        float ex = __expf(a);
        g_attn[e * 4 + h] = ex;
        atomicAdd(&g_sum[dst * 4 + h], ex);
    }
}

// ---------------- weighted-V scatter (warp per edge, red.v4) -----------------
__global__ __launch_bounds__(256) void k_scatter(const int* __restrict__ ei) {
    int e = blockIdx.x * 8 + (threadIdx.x >> 5);
    if (e >= N_EDGES) return;
    int lane = threadIdx.x & 31;
    int src = ei[e];
    int dst = ei[N_EDGES + e];
    int h = lane >> 3;
    float ex = g_attn[e * 4 + h];
    float s = g_sum[dst * 4 + h];
    float w = ex / fmaxf(s, 1e-12f);
    float4 v = ((const float4*)(g_V + (size_t)src * 128))[lane];
    float* p = g_agg + (size_t)dst * 128 + lane * 4;
    asm volatile("red.global.add.v4.f32 [%0], {%1, %2, %3, %4};"
                 :: "l"(p), "f"(v.x * w), "f"(v.y * w), "f"(v.z * w), "f"(v.w * w)
                 : "memory");
}

// ---------------- output GEMM: relu(x@Wm_x + agg@Wf + bf), packed f32x2 ------
__global__ __launch_bounds__(256) void k_out(const float* __restrict__ x,
                                             const float* __restrict__ Wm,
                                             float* __restrict__ out) {
    int rg = threadIdx.x >> 4;
    int c0 = (threadIdx.x & 15) * 8;
    int r0 = blockIdx.x * 64 + rg * 4;

    int rr[4];
    #pragma unroll
    for (int r = 0; r < 4; r++) {
        int ri = r0 + r;
        rr[r] = ri < N_NODES ? ri : (N_NODES - 1);
    }

    unsigned long long acc[4][4];
    #pragma unroll
    for (int r = 0; r < 4; r++)
        #pragma unroll
        for (int c = 0; c < 4; c++) acc[r][c] = 0ull;

    #pragma unroll 4
    for (int k = 0; k < 128; k++) {
        float4 w0 = *(const float4*)(Wm + k * 128 + c0);
        float4 w1 = *(const float4*)(Wm + k * 128 + c0 + 4);
        unsigned long long wp0 = pack2(w0.x, w0.y);
        unsigned long long wp1 = pack2(w0.z, w0.w);
        unsigned long long wp2 = pack2(w1.x, w1.y);
        unsigned long long wp3 = pack2(w1.z, w1.w);
        #pragma unroll
        for (int r = 0; r < 4; r++) {
            unsigned long long xp = dup2(x[(size_t)rr[r] * 128 + k]);
            fma2(acc[r][0], xp, wp0);
            fma2(acc[r][1], xp, wp1);
            fma2(acc[r][2], xp, wp2);
            fma2(acc[r][3], xp, wp3);
        }
    }

    #pragma unroll 4
    for (int k = 0; k < 128; k++) {
        float4 w0 = *(const float4*)(g_Wf + k * 128 + c0);
        float4 w1 = *(const float4*)(g_Wf + k * 128 + c0 + 4);
        unsigned long long wp0 = pack2(w0.x, w0.y);
        unsigned long long wp1 = pack2(w0.z, w0.w);
        unsigned long long wp2 = pack2(w1.x, w1.y);
        unsigned long long wp3 = pack2(w1.z, w1.w);
        #pragma unroll
        for (int r = 0; r < 4; r++) {
            unsigned long long ap = dup2(g_agg[(size_t)rr[r] * 128 + k]);
            fma2(acc[r][0], ap, wp0);
            fma2(acc[r][1], ap, wp1);
            fma2(acc[r][2], ap, wp2);
            fma2(acc[r][3], ap, wp3);
        }
    }

    float4 b0 = *(const float4*)(g_bf + c0);
    float4 b1 = *(const float4*)(g_bf + c0 + 4);
    float bb[8] = {b0.x, b0.y, b0.z, b0.w, b1.x, b1.y, b1.z, b1.w};
    #pragma unroll
    for (int r = 0; r < 4; r++) {
        if (r0 + r < N_NODES) {
            float o[8];
            #pragma unroll
            for (int c = 0; c < 4; c++) unpack2(acc[r][c], o[c * 2], o[c * 2 + 1]);
            #pragma unroll
            for (int c = 0; c < 8; c++) o[c] = fmaxf(o[c] + bb[c], 0.f);
            float4* p = (float4*)(out + (size_t)(r0 + r) * 128 + c0);
            p[0] = make_float4(o[0], o[1], o[2], o[3]);
            p[1] = make_float4(o[4], o[5], o[6], o[7]);
        }
    }
}

// ---------------- launch ------------------------------------------------------
extern "C" void kernel_launch(void* const* d_in, const int* in_sizes, int n_in,
                              void* d_out, int out_size) {
    const float* x  = (const float*)d_in[0];
    const int*   ei = (const int*)d_in[1];
    const float* ea = (const float*)d_in[2];
    const float* Wq = (const float*)d_in[3];
    const float* Wk = (const float*)d_in[4];
    const float* Wv = (const float*)d_in[5];
    const float* We = (const float*)d_in[6];
    const float* Wo = (const float*)d_in[7];
    const float* bo = (const float*)d_in[8];
    const float* Wm = (const float*)d_in[9];
    const float* bm = (const float*)d_in[10];
    float* out = (float*)d_out;

    k_init<<<(N_NODES * 32 + 255) / 256, 256>>>();
    k_fusew<<<128, 128>>>(Wo, Wm, bo, bm);
    k_qkv<<<dim3((N_NODES + 63) / 64, 3), 256>>>(x, Wq, Wk, Wv);
    k_attn<<<(N_EDGES + 7) / 8, 256>>>(ei, ea, We);
    k_scatter<<<(N_EDGES + 7) / 8, 256>>>(ei);
    k_out<<<(N_NODES + 63) / 64, 256>>>(x, Wm, out);
}

// round 4
// speedup vs baseline: 1.0689x; 1.0689x over previous
#include <cuda_runtime.h>

#define N_NODES 50000
#define N_EDGES 800000
#define HD_SCALE 0.17677669529663687f   // 1/sqrt(32)
#define SCAN_T 1024

// ---------------- scratch (device globals: no allocation allowed) ----------
__device__ __align__(256) float g_Q[N_NODES * 128];
__device__ __align__(256) float g_K[N_NODES * 128];
__device__ __align__(256) float g_V[N_NODES * 128];
__device__ __align__(256) float g_attn[N_EDGES * 4];   // exp(logit)
__device__ __align__(256) float g_agg[N_NODES * 128];
__device__ __align__(256) float g_Wf[128 * 128];
__device__ __align__(256) float g_bf[128];
__device__ __align__(256) int   g_cnt[N_NODES];        // in-degree histogram
__device__ __align__(256) int   g_off[N_NODES + 1];    // CSR offsets
__device__ __align__(256) int   g_pos[N_NODES];        // bucket cursors
__device__ __align__(256) int   g_eid[N_EDGES];        // edge ids sorted by dst

// ---------------- init: zero histogram --------------------------------------
__global__ void k_init() {
    int i = blockIdx.x * 256 + threadIdx.x;
    if (i < N_NODES) g_cnt[i] = 0;
}

// ---------------- fuse Wo into Wm lower half --------------------------------
__global__ void k_fusew(const float* __restrict__ Wo, const float* __restrict__ Wm,
                        const float* __restrict__ bo, const float* __restrict__ bm) {
    int r = blockIdx.x;        // 0..127
    int j = threadIdx.x;       // 0..127
    float acc = 0.f;
    #pragma unroll 8
    for (int k = 0; k < 128; k++)
        acc += Wo[r * 128 + k] * Wm[(128 + k) * 128 + j];
    g_Wf[r * 128 + j] = acc;
    if (r == 0) {
        float b = bm[j];
        #pragma unroll 8
        for (int k = 0; k < 128; k++)
            b += bo[k] * Wm[(128 + k) * 128 + j];
        g_bf[j] = b;
    }
}

// ---------------- QKV GEMM: [N,128] @ [128,128] x3 (R2 scalar form) ---------
__global__ __launch_bounds__(256) void k_qkv(const float* __restrict__ x,
                                             const float* __restrict__ Wq,
                                             const float* __restrict__ Wk,
                                             const float* __restrict__ Wv) {
    const float* W;
    float* out;
    if (blockIdx.y == 0)      { W = Wq; out = g_Q; }
    else if (blockIdx.y == 1) { W = Wk; out = g_K; }
    else                      { W = Wv; out = g_V; }

    int rg = threadIdx.x >> 4;                 // 0..15
    int c0 = (threadIdx.x & 15) * 8;           // 0..120
    int r0 = blockIdx.x * 64 + rg * 4;

    int rr[4];
    #pragma unroll
    for (int r = 0; r < 4; r++) {
        int ri = r0 + r;
        rr[r] = ri < N_NODES ? ri : (N_NODES - 1);
    }

    float acc[4][8];
    #pragma unroll
    for (int r = 0; r < 4; r++)
        #pragma unroll
        for (int c = 0; c < 8; c++) acc[r][c] = 0.f;

    #pragma unroll 4
    for (int k = 0; k < 128; k++) {
        float4 w0 = *(const float4*)(W + k * 128 + c0);
        float4 w1 = *(const float4*)(W + k * 128 + c0 + 4);
        float xv[4];
        #pragma unroll
        for (int r = 0; r < 4; r++) xv[r] = x[(size_t)rr[r] * 128 + k];
        #pragma unroll
        for (int r = 0; r < 4; r++) {
            acc[r][0] = fmaf(xv[r], w0.x, acc[r][0]);
            acc[r][1] = fmaf(xv[r], w0.y, acc[r][1]);
            acc[r][2] = fmaf(xv[r], w0.z, acc[r][2]);
            acc[r][3] = fmaf(xv[r], w0.w, acc[r][3]);
            acc[r][4] = fmaf(xv[r], w1.x, acc[r][4]);
            acc[r][5] = fmaf(xv[r], w1.y, acc[r][5]);
            acc[r][6] = fmaf(xv[r], w1.z, acc[r][6]);
            acc[r][7] = fmaf(xv[r], w1.w, acc[r][7]);
        }
    }

    #pragma unroll
    for (int r = 0; r < 4; r++) {
        if (r0 + r < N_NODES) {
            float4* o = (float4*)(out + (size_t)(r0 + r) * 128 + c0);
            o[0] = make_float4(acc[r][0], acc[r][1], acc[r][2], acc[r][3]);
            o[1] = make_float4(acc[r][4], acc[r][5], acc[r][6], acc[r][7]);
        }
    }
}

// ---------------- attention: thread per (e,h), exp, + degree histogram -------
__global__ __launch_bounds__(256) void k_attn(const int* __restrict__ ei,
                                              const float* __restrict__ ea,
                                              const float* __restrict__ We) {
    int idx = blockIdx.x * 256 + threadIdx.x;
    if (idx >= N_EDGES * 4) return;
    int e = idx >> 2, h = idx & 3;
    int src = ei[e];
    int dst = ei[N_EDGES + e];
    if (h == 0) atomicAdd(&g_cnt[dst], 1);

    const float4* q = (const float4*)(g_Q + (size_t)dst * 128 + h * 32);
    const float4* kk = (const float4*)(g_K + (size_t)src * 128 + h * 32);
    float acc = 0.f;
    #pragma unroll
    for (int i = 0; i < 8; i++) {
        float4 qa = q[i], kb = kk[i];
        acc += qa.x * kb.x + qa.y * kb.y + qa.z * kb.z + qa.w * kb.w;
    }
    float b = ea[e * 3 + 0] * We[0 * 4 + h]
            + ea[e * 3 + 1] * We[1 * 4 + h]
            + ea[e * 3 + 2] * We[2 * 4 + h];
    float a = acc * HD_SCALE + b;
    a = a >= 0.f ? a : 0.2f * a;        // leaky_relu(0.2)
    // global max stabilizer cancels exactly in per-(dst,h) normalization;
    // logits are O(10), exp is safe in fp32 (verified R3, rel_err 4e-7).
    g_attn[idx] = __expf(a);
}

// ---------------- single-block exclusive scan of degrees --------------------
__global__ __launch_bounds__(SCAN_T) void k_scan() {
    __shared__ int sh[SCAN_T];
    int t = threadIdx.x;
    const int CHUNK = (N_NODES + SCAN_T - 1) / SCAN_T;  // 49
    int beg = t * CHUNK;
    int end = beg + CHUNK < N_NODES ? beg + CHUNK : N_NODES;
    int s = 0;
    for (int i = beg; i < end; i++) s += g_cnt[i];
    sh[t] = s;
    __syncthreads();
    // Hillis-Steele inclusive scan
    for (int o = 1; o < SCAN_T; o <<= 1) {
        int v = (t >= o) ? sh[t - o] : 0;
        __syncthreads();
        sh[t] += v;
        __syncthreads();
    }
    int run = (t > 0) ? sh[t - 1] : 0;   // exclusive prefix of this chunk
    for (int i = beg; i < end; i++) {
        int c = g_cnt[i];
        g_off[i] = run;
        g_pos[i] = run;
        run += c;
    }
    if (beg < N_NODES && end == N_NODES) g_off[N_NODES] = run;
}

// ---------------- bucket fill: edge ids grouped by dst ----------------------
__global__ __launch_bounds__(256) void k_bucket(const int* __restrict__ ei) {
    int e = blockIdx.x * 256 + threadIdx.x;
    if (e >= N_EDGES) return;
    int dst = ei[N_EDGES + e];
    int p = atomicAdd(&g_pos[dst], 1);
    g_eid[p] = e;
}

// ---------------- gather: warp per dst node, softmax-normalized V sum --------
__global__ __launch_bounds__(256) void k_gather(const int* __restrict__ ei) {
    int n = blockIdx.x * 8 + (threadIdx.x >> 5);
    if (n >= N_NODES) return;
    int lane = threadIdx.x & 31;
    int h = lane >> 3;                 // head owning this float4
    int beg = g_off[n];
    int end = g_off[n + 1];

    float4 acc = make_float4(0.f, 0.f, 0.f, 0.f);
    float s = 0.f;
    for (int i = beg; i < end; i++) {
        int e = g_eid[i];              // broadcast (same addr all lanes)
        int src = ei[e];               // broadcast
        float ex = g_attn[e * 4 + h];  // broadcast within 8-lane head group
        float4 v = ((const float4*)(g_V + (size_t)src * 128))[lane];
        s += ex;
        acc.x = fmaf(v.x, ex, acc.x);
        acc.y = fmaf(v.y, ex, acc.y);
        acc.z = fmaf(v.z, ex, acc.z);
        acc.w = fmaf(v.w, ex, acc.w);
    }
    float inv = 1.f / fmaxf(s, 1e-12f);
    float4* o = (float4*)(g_agg + (size_t)n * 128);
    o[lane] = make_float4(acc.x * inv, acc.y * inv, acc.z * inv, acc.w * inv);
}

// ---------------- output GEMM: relu(x@Wm_x + agg@Wf + bf) (R2 scalar) --------
__global__ __launch_bounds__(256) void k_out(const float* __restrict__ x,
                                             const float* __restrict__ Wm,
                                             float* __restrict__ out) {
    int rg = threadIdx.x >> 4;
    int c0 = (threadIdx.x & 15) * 8;
    int r0 = blockIdx.x * 64 + rg * 4;

    int rr[4];
    #pragma unroll
    for (int r = 0; r < 4; r++) {
        int ri = r0 + r;
        rr[r] = ri < N_NODES ? ri : (N_NODES - 1);
    }

    float acc[4][8];
    #pragma unroll
    for (int r = 0; r < 4; r++)
        #pragma unroll
        for (int c = 0; c < 8; c++) acc[r][c] = 0.f;

    #pragma unroll 4
    for (int k = 0; k < 128; k++) {
        float4 w0 = *(const float4*)(Wm + k * 128 + c0);
        float4 w1 = *(const float4*)(Wm + k * 128 + c0 + 4);
        float xv[4];
        #pragma unroll
        for (int r = 0; r < 4; r++) xv[r] = x[(size_t)rr[r] * 128 + k];
        #pragma unroll
        for (int r = 0; r < 4; r++) {
            acc[r][0] = fmaf(xv[r], w0.x, acc[r][0]);
            acc[r][1] = fmaf(xv[r], w0.y, acc[r][1]);
            acc[r][2] = fmaf(xv[r], w0.z, acc[r][2]);
            acc[r][3] = fmaf(xv[r], w0.w, acc[r][3]);
            acc[r][4] = fmaf(xv[r], w1.x, acc[r][4]);
            acc[r][5] = fmaf(xv[r], w1.y, acc[r][5]);
            acc[r][6] = fmaf(xv[r], w1.z, acc[r][6]);
            acc[r][7] = fmaf(xv[r], w1.w, acc[r][7]);
        }
    }

    #pragma unroll 4
    for (int k = 0; k < 128; k++) {
        float4 w0 = *(const float4*)(g_Wf + k * 128 + c0);
        float4 w1 = *(const float4*)(g_Wf + k * 128 + c0 + 4);
        float av[4];
        #pragma unroll
        for (int r = 0; r < 4; r++) av[r] = g_agg[(size_t)rr[r] * 128 + k];
        #pragma unroll
        for (int r = 0; r < 4; r++) {
            acc[r][0] = fmaf(av[r], w0.x, acc[r][0]);
            acc[r][1] = fmaf(av[r], w0.y, acc[r][1]);
            acc[r][2] = fmaf(av[r], w0.z, acc[r][2]);
            acc[r][3] = fmaf(av[r], w0.w, acc[r][3]);
            acc[r][4] = fmaf(av[r], w1.x, acc[r][4]);
            acc[r][5] = fmaf(av[r], w1.y, acc[r][5]);
            acc[r][6] = fmaf(av[r], w1.z, acc[r][6]);
            acc[r][7] = fmaf(av[r], w1.w, acc[r][7]);
        }
    }

    float4 b0 = *(const float4*)(g_bf + c0);
    float4 b1 = *(const float4*)(g_bf + c0 + 4);
    #pragma unroll
    for (int r = 0; r < 4; r++) {
        if (r0 + r < N_NODES) {
            float4* o = (float4*)(out + (size_t)(r0 + r) * 128 + c0);
            o[0] = make_float4(fmaxf(acc[r][0] + b0.x, 0.f), fmaxf(acc[r][1] + b0.y, 0.f),
                               fmaxf(acc[r][2] + b0.z, 0.f), fmaxf(acc[r][3] + b0.w, 0.f));
            o[1] = make_float4(fmaxf(acc[r][4] + b1.x, 0.f), fmaxf(acc[r][5] + b1.y, 0.f),
                               fmaxf(acc[r][6] + b1.z, 0.f), fmaxf(acc[r][7] + b1.w, 0.f));
        }
    }
}

// ---------------- launch ------------------------------------------------------
extern "C" void kernel_launch(void* const* d_in, const int* in_sizes, int n_in,
                              void* d_out, int out_size) {
    const float* x  = (const float*)d_in[0];
    const int*   ei = (const int*)d_in[1];
    const float* ea = (const float*)d_in[2];
    const float* Wq = (const float*)d_in[3];
    const float* Wk = (const float*)d_in[4];
    const float* Wv = (const float*)d_in[5];
    const float* We = (const float*)d_in[6];
    const float* Wo = (const float*)d_in[7];
    const float* bo = (const float*)d_in[8];
    const float* Wm = (const float*)d_in[9];
    const float* bm = (const float*)d_in[10];
    float* out = (float*)d_out;

    k_init<<<(N_NODES + 255) / 256, 256>>>();
    k_fusew<<<128, 128>>>(Wo, Wm, bo, bm);
    k_qkv<<<dim3((N_NODES + 63) / 64, 3), 256>>>(x, Wq, Wk, Wv);
    k_attn<<<(N_EDGES * 4 + 255) / 256, 256>>>(ei, ea, We);
    k_scan<<<1, SCAN_T>>>();
    k_bucket<<<(N_EDGES + 255) / 256, 256>>>(ei);
    k_gather<<<(N_NODES + 7) / 8, 256>>>(ei);
    k_out<<<(N_NODES + 63) / 64, 256>>>(x, Wm, out);
}

// round 5
// speedup vs baseline: 1.1385x; 1.0652x over previous
#include <cuda_runtime.h>

#define N_NODES 50000
#define N_EDGES 800000
#define HD_SCALE 0.17677669529663687f   // 1/sqrt(32)
#define SCAN_T 1024

// ---------------- scratch (device globals: no allocation allowed) ----------
__device__ __align__(256) float g_Q[N_NODES * 128];
__device__ __align__(256) float g_K[N_NODES * 128];
__device__ __align__(256) float g_V[N_NODES * 128];
__device__ __align__(256) float g_bias[N_EDGES * 4];   // edge_attr @ We
__device__ __align__(256) float g_agg[N_NODES * 128];
__device__ __align__(256) float g_Wf[128 * 128];
__device__ __align__(256) float g_bf[128];
__device__ __align__(256) int   g_cnt[N_NODES];        // in-degree histogram
__device__ __align__(256) int   g_off[N_NODES + 1];    // CSR offsets
__device__ __align__(256) int   g_pos[N_NODES];        // bucket cursors
__device__ __align__(256) int   g_eid[N_EDGES];        // edge ids sorted by dst

// ---------------- init: zero histogram --------------------------------------
__global__ void k_init() {
    int i = blockIdx.x * 256 + threadIdx.x;
    if (i < N_NODES) g_cnt[i] = 0;
}

// ---------------- fuse Wo into Wm lower half --------------------------------
__global__ void k_fusew(const float* __restrict__ Wo, const float* __restrict__ Wm,
                        const float* __restrict__ bo, const float* __restrict__ bm) {
    int r = blockIdx.x;        // 0..127
    int j = threadIdx.x;       // 0..127
    float acc = 0.f;
    #pragma unroll 8
    for (int k = 0; k < 128; k++)
        acc += Wo[r * 128 + k] * Wm[(128 + k) * 128 + j];
    g_Wf[r * 128 + j] = acc;
    if (r == 0) {
        float b = bm[j];
        #pragma unroll 8
        for (int k = 0; k < 128; k++)
            b += bo[k] * Wm[(128 + k) * 128 + j];
        g_bf[j] = b;
    }
}

// ---------------- QKV GEMM: [N,128] @ [128,128] x3 --------------------------
__global__ __launch_bounds__(256) void k_qkv(const float* __restrict__ x,
                                             const float* __restrict__ Wq,
                                             const float* __restrict__ Wk,
                                             const float* __restrict__ Wv) {
    const float* W;
    float* out;
    if (blockIdx.y == 0)      { W = Wq; out = g_Q; }
    else if (blockIdx.y == 1) { W = Wk; out = g_K; }
    else                      { W = Wv; out = g_V; }

    int rg = threadIdx.x >> 4;                 // 0..15
    int c0 = (threadIdx.x & 15) * 8;           // 0..120
    int r0 = blockIdx.x * 64 + rg * 4;

    int rr[4];
    #pragma unroll
    for (int r = 0; r < 4; r++) {
        int ri = r0 + r;
        rr[r] = ri < N_NODES ? ri : (N_NODES - 1);
    }

    float acc[4][8];
    #pragma unroll
    for (int r = 0; r < 4; r++)
        #pragma unroll
        for (int c = 0; c < 8; c++) acc[r][c] = 0.f;

    #pragma unroll 4
    for (int k = 0; k < 128; k++) {
        float4 w0 = *(const float4*)(W + k * 128 + c0);
        float4 w1 = *(const float4*)(W + k * 128 + c0 + 4);
        float xv[4];
        #pragma unroll
        for (int r = 0; r < 4; r++) xv[r] = x[(size_t)rr[r] * 128 + k];
        #pragma unroll
        for (int r = 0; r < 4; r++) {
            acc[r][0] = fmaf(xv[r], w0.x, acc[r][0]);
            acc[r][1] = fmaf(xv[r], w0.y, acc[r][1]);
            acc[r][2] = fmaf(xv[r], w0.z, acc[r][2]);
            acc[r][3] = fmaf(xv[r], w0.w, acc[r][3]);
            acc[r][4] = fmaf(xv[r], w1.x, acc[r][4]);
            acc[r][5] = fmaf(xv[r], w1.y, acc[r][5]);
            acc[r][6] = fmaf(xv[r], w1.z, acc[r][6]);
            acc[r][7] = fmaf(xv[r], w1.w, acc[r][7]);
        }
    }

    #pragma unroll
    for (int r = 0; r < 4; r++) {
        if (r0 + r < N_NODES) {
            float4* o = (float4*)(out + (size_t)(r0 + r) * 128 + c0);
            o[0] = make_float4(acc[r][0], acc[r][1], acc[r][2], acc[r][3]);
            o[1] = make_float4(acc[r][4], acc[r][5], acc[r][6], acc[r][7]);
        }
    }
}

// ---------------- histogram + edge bias precompute ---------------------------
__global__ __launch_bounds__(256) void k_hist(const int* __restrict__ ei,
                                              const float* __restrict__ ea,
                                              const float* __restrict__ We) {
    int e = blockIdx.x * 256 + threadIdx.x;
    if (e >= N_EDGES) return;
    int dst = ei[N_EDGES + e];
    atomicAdd(&g_cnt[dst], 1);
    float a0 = ea[e * 3 + 0], a1 = ea[e * 3 + 1], a2 = ea[e * 3 + 2];
    float4 b;
    b.x = a0 * We[0] + a1 * We[4] + a2 * We[8];
    b.y = a0 * We[1] + a1 * We[5] + a2 * We[9];
    b.z = a0 * We[2] + a1 * We[6] + a2 * We[10];
    b.w = a0 * We[3] + a1 * We[7] + a2 * We[11];
    ((float4*)g_bias)[e] = b;
}

// ---------------- single-block exclusive scan of degrees --------------------
__global__ __launch_bounds__(SCAN_T) void k_scan() {
    __shared__ int sh[SCAN_T];
    int t = threadIdx.x;
    const int CHUNK = (N_NODES + SCAN_T - 1) / SCAN_T;  // 49
    int beg = t * CHUNK;
    int end = beg + CHUNK < N_NODES ? beg + CHUNK : N_NODES;
    int s = 0;
    for (int i = beg; i < end; i++) s += g_cnt[i];
    sh[t] = s;
    __syncthreads();
    for (int o = 1; o < SCAN_T; o <<= 1) {
        int v = (t >= o) ? sh[t - o] : 0;
        __syncthreads();
        sh[t] += v;
        __syncthreads();
    }
    int run = (t > 0) ? sh[t - 1] : 0;
    for (int i = beg; i < end; i++) {
        int c = g_cnt[i];
        g_off[i] = run;
        g_pos[i] = run;
        run += c;
    }
    if (beg < N_NODES && end == N_NODES) g_off[N_NODES] = run;
}

// ---------------- bucket fill: edge ids grouped by dst ----------------------
__global__ __launch_bounds__(256) void k_bucket(const int* __restrict__ ei) {
    int e = blockIdx.x * 256 + threadIdx.x;
    if (e >= N_EDGES) return;
    int dst = ei[N_EDGES + e];
    int p = atomicAdd(&g_pos[dst], 1);
    g_eid[p] = e;
}

// ---------------- fused attention + gather: warp per dst node ----------------
__global__ __launch_bounds__(256) void k_gather(const int* __restrict__ ei) {
    int n = blockIdx.x * 8 + (threadIdx.x >> 5);
    if (n >= N_NODES) return;
    int lane = threadIdx.x & 31;
    int h = lane >> 3;                 // head of this lane's float4
    int beg = g_off[n];
    int end = g_off[n + 1];

    float4 q = ((const float4*)(g_Q + (size_t)n * 128))[lane];
    float4 acc = make_float4(0.f, 0.f, 0.f, 0.f);
    float s = 0.f;

    // 1-deep prefetch of the eid -> src index chain
    int e_nxt = 0, src_nxt = 0;
    if (beg < end) { e_nxt = g_eid[beg]; src_nxt = ei[e_nxt]; }

    for (int i = beg; i < end; i++) {
        int e = e_nxt, src = src_nxt;
        if (i + 1 < end) { e_nxt = g_eid[i + 1]; src_nxt = ei[e_nxt]; }

        float bias = g_bias[e * 4 + h];                        // bcast per 8 lanes
        float4 k = ((const float4*)(g_K + (size_t)src * 128))[lane];
        float4 v = ((const float4*)(g_V + (size_t)src * 128))[lane];

        float p = q.x * k.x + q.y * k.y + q.z * k.z + q.w * k.w;
        p += __shfl_xor_sync(0xffffffffu, p, 1);
        p += __shfl_xor_sync(0xffffffffu, p, 2);
        p += __shfl_xor_sync(0xffffffffu, p, 4);   // all 8 lanes have head dot

        float a = p * HD_SCALE + bias;
        a = a >= 0.f ? a : 0.2f * a;               // leaky_relu(0.2)
        // global-max stabilizer cancels in per-(dst,h) normalization;
        // logits O(10) -> exp safe in fp32 (verified R3/R4, rel_err 4e-7)
        float ex = __expf(a);
        s += ex;
        acc.x = fmaf(v.x, ex, acc.x);
        acc.y = fmaf(v.y, ex, acc.y);
        acc.z = fmaf(v.z, ex, acc.z);
        acc.w = fmaf(v.w, ex, acc.w);
    }

    float inv = 1.f / fmaxf(s, 1e-12f);
    float4* o = (float4*)(g_agg + (size_t)n * 128);
    o[lane] = make_float4(acc.x * inv, acc.y * inv, acc.z * inv, acc.w * inv);
}

// ---------------- output GEMM: relu(x@Wm_x + agg@Wf + bf) --------------------
__global__ __launch_bounds__(256) void k_out(const float* __restrict__ x,
                                             const float* __restrict__ Wm,
                                             float* __restrict__ out) {
    int rg = threadIdx.x >> 4;
    int c0 = (threadIdx.x & 15) * 8;
    int r0 = blockIdx.x * 64 + rg * 4;

    int rr[4];
    #pragma unroll
    for (int r = 0; r < 4; r++) {
        int ri = r0 + r;
        rr[r] = ri < N_NODES ? ri : (N_NODES - 1);
    }

    float acc[4][8];
    #pragma unroll
    for (int r = 0; r < 4; r++)
        #pragma unroll
        for (int c = 0; c < 8; c++) acc[r][c] = 0.f;

    #pragma unroll 4
    for (int k = 0; k < 128; k++) {
        float4 w0 = *(const float4*)(Wm + k * 128 + c0);
        float4 w1 = *(const float4*)(Wm + k * 128 + c0 + 4);
        float xv[4];
        #pragma unroll
        for (int r = 0; r < 4; r++) xv[r] = x[(size_t)rr[r] * 128 + k];
        #pragma unroll
        for (int r = 0; r < 4; r++) {
            acc[r][0] = fmaf(xv[r], w0.x, acc[r][0]);
            acc[r][1] = fmaf(xv[r], w0.y, acc[r][1]);
            acc[r][2] = fmaf(xv[r], w0.z, acc[r][2]);
            acc[r][3] = fmaf(xv[r], w0.w, acc[r][3]);
            acc[r][4] = fmaf(xv[r], w1.x, acc[r][4]);
            acc[r][5] = fmaf(xv[r], w1.y, acc[r][5]);
            acc[r][6] = fmaf(xv[r], w1.z, acc[r][6]);
            acc[r][7] = fmaf(xv[r], w1.w, acc[r][7]);
        }
    }

    #pragma unroll 4
    for (int k = 0; k < 128; k++) {
        float4 w0 = *(const float4*)(g_Wf + k * 128 + c0);
        float4 w1 = *(const float4*)(g_Wf + k * 128 + c0 + 4);
        float av[4];
        #pragma unroll
        for (int r = 0; r < 4; r++) av[r] = g_agg[(size_t)rr[r] * 128 + k];
        #pragma unroll
        for (int r = 0; r < 4; r++) {
            acc[r][0] = fmaf(av[r], w0.x, acc[r][0]);
            acc[r][1] = fmaf(av[r], w0.y, acc[r][1]);
            acc[r][2] = fmaf(av[r], w0.z, acc[r][2]);
            acc[r][3] = fmaf(av[r], w0.w, acc[r][3]);
            acc[r][4] = fmaf(av[r], w1.x, acc[r][4]);
            acc[r][5] = fmaf(av[r], w1.y, acc[r][5]);
            acc[r][6] = fmaf(av[r], w1.z, acc[r][6]);
            acc[r][7] = fmaf(av[r], w1.w, acc[r][7]);
        }
    }

    float4 b0 = *(const float4*)(g_bf + c0);
    float4 b1 = *(const float4*)(g_bf + c0 + 4);
    #pragma unroll
    for (int r = 0; r < 4; r++) {
        if (r0 + r < N_NODES) {
            float4* o = (float4*)(out + (size_t)(r0 + r) * 128 + c0);
            o[0] = make_float4(fmaxf(acc[r][0] + b0.x, 0.f), fmaxf(acc[r][1] + b0.y, 0.f),
                               fmaxf(acc[r][2] + b0.z, 0.f), fmaxf(acc[r][3] + b0.w, 0.f));
            o[1] = make_float4(fmaxf(acc[r][4] + b1.x, 0.f), fmaxf(acc[r][5] + b1.y, 0.f),
                               fmaxf(acc[r][6] + b1.z, 0.f), fmaxf(acc[r][7] + b1.w, 0.f));
        }
    }
}

// ---------------- launch ------------------------------------------------------
extern "C" void kernel_launch(void* const* d_in, const int* in_sizes, int n_in,
                              void* d_out, int out_size) {
    const float* x  = (const float*)d_in[0];
    const int*   ei = (const int*)d_in[1];
    const float* ea = (const float*)d_in[2];
    const float* Wq = (const float*)d_in[3];
    const float* Wk = (const float*)d_in[4];
    const float* Wv = (const float*)d_in[5];
    const float* We = (const float*)d_in[6];
    const float* Wo = (const float*)d_in[7];
    const float* bo = (const float*)d_in[8];
    const float* Wm = (const float*)d_in[9];
    const float* bm = (const float*)d_in[10];
    float* out = (float*)d_out;

    k_init<<<(N_NODES + 255) / 256, 256>>>();
    k_hist<<<(N_EDGES + 255) / 256, 256>>>(ei, ea, We);
    k_scan<<<1, SCAN_T>>>();
    k_bucket<<<(N_EDGES + 255) / 256, 256>>>(ei);
    k_fusew<<<128, 128>>>(Wo, Wm, bo, bm);
    k_qkv<<<dim3((N_NODES + 63) / 64, 3), 256>>>(x, Wq, Wk, Wv);
    k_gather<<<(N_NODES + 7) / 8, 256>>>(ei);
    k_out<<<(N_NODES + 63) / 64, 256>>>(x, Wm, out);
}

// round 6
// speedup vs baseline: 1.1791x; 1.0356x over previous
#include <cuda_runtime.h>

#define N_NODES 50000
#define N_EDGES 800000
#define HD_SCALE 0.17677669529663687f   // 1/sqrt(32)
#define SCAN_T 1024

// ---------------- scratch (device globals: no allocation allowed) ----------
__device__ __align__(256) float g_Q[N_NODES * 128];
__device__ __align__(256) float g_K[N_NODES * 128];
__device__ __align__(256) float g_V[N_NODES * 128];
__device__ __align__(256) float g_biasS[N_EDGES * 4];  // edge bias, CSR order
__device__ __align__(256) float g_agg[N_NODES * 128];
__device__ __align__(256) float g_Wf[128 * 128];
__device__ __align__(256) float g_bf[128];
__device__ __align__(256) int   g_cnt[N_NODES];        // in-degree histogram
__device__ __align__(256) int   g_off[N_NODES + 1];    // CSR offsets
__device__ __align__(256) int   g_pos[N_NODES];        // bucket cursors
__device__ __align__(256) int   g_src[N_EDGES];        // src node, CSR order

// ---------------- init: zero histogram --------------------------------------
__global__ void k_init() {
    int i = blockIdx.x * 256 + threadIdx.x;
    if (i < N_NODES) g_cnt[i] = 0;
}

// ---------------- degree histogram -------------------------------------------
__global__ __launch_bounds__(256) void k_hist(const int* __restrict__ ei) {
    int e = blockIdx.x * 256 + threadIdx.x;
    if (e >= N_EDGES) return;
    atomicAdd(&g_cnt[ei[N_EDGES + e]], 1);
}

// ---------------- fuse Wo into Wm lower half --------------------------------
__global__ void k_fusew(const float* __restrict__ Wo, const float* __restrict__ Wm,
                        const float* __restrict__ bo, const float* __restrict__ bm) {
    int r = blockIdx.x;        // 0..127
    int j = threadIdx.x;       // 0..127
    float acc = 0.f;
    #pragma unroll 8
    for (int k = 0; k < 128; k++)
        acc += Wo[r * 128 + k] * Wm[(128 + k) * 128 + j];
    g_Wf[r * 128 + j] = acc;
    if (r == 0) {
        float b = bm[j];
        #pragma unroll 8
        for (int k = 0; k < 128; k++)
            b += bo[k] * Wm[(128 + k) * 128 + j];
        g_bf[j] = b;
    }
}

// ---------------- QKV GEMM: [N,128] @ [128,128] x3 --------------------------
__global__ __launch_bounds__(256) void k_qkv(const float* __restrict__ x,
                                             const float* __restrict__ Wq,
                                             const float* __restrict__ Wk,
                                             const float* __restrict__ Wv) {
    const float* W;
    float* out;
    if (blockIdx.y == 0)      { W = Wq; out = g_Q; }
    else if (blockIdx.y == 1) { W = Wk; out = g_K; }
    else                      { W = Wv; out = g_V; }

    int rg = threadIdx.x >> 4;                 // 0..15
    int c0 = (threadIdx.x & 15) * 8;           // 0..120
    int r0 = blockIdx.x * 64 + rg * 4;

    int rr[4];
    #pragma unroll
    for (int r = 0; r < 4; r++) {
        int ri = r0 + r;
        rr[r] = ri < N_NODES ? ri : (N_NODES - 1);
    }

    float acc[4][8];
    #pragma unroll
    for (int r = 0; r < 4; r++)
        #pragma unroll
        for (int c = 0; c < 8; c++) acc[r][c] = 0.f;

    #pragma unroll 4
    for (int k = 0; k < 128; k++) {
        float4 w0 = *(const float4*)(W + k * 128 + c0);
        float4 w1 = *(const float4*)(W + k * 128 + c0 + 4);
        float xv[4];
        #pragma unroll
        for (int r = 0; r < 4; r++) xv[r] = x[(size_t)rr[r] * 128 + k];
        #pragma unroll
        for (int r = 0; r < 4; r++) {
            acc[r][0] = fmaf(xv[r], w0.x, acc[r][0]);
            acc[r][1] = fmaf(xv[r], w0.y, acc[r][1]);
            acc[r][2] = fmaf(xv[r], w0.z, acc[r][2]);
            acc[r][3] = fmaf(xv[r], w0.w, acc[r][3]);
            acc[r][4] = fmaf(xv[r], w1.x, acc[r][4]);
            acc[r][5] = fmaf(xv[r], w1.y, acc[r][5]);
            acc[r][6] = fmaf(xv[r], w1.z, acc[r][6]);
            acc[r][7] = fmaf(xv[r], w1.w, acc[r][7]);
        }
    }

    #pragma unroll
    for (int r = 0; r < 4; r++) {
        if (r0 + r < N_NODES) {
            float4* o = (float4*)(out + (size_t)(r0 + r) * 128 + c0);
            o[0] = make_float4(acc[r][0], acc[r][1], acc[r][2], acc[r][3]);
            o[1] = make_float4(acc[r][4], acc[r][5], acc[r][6], acc[r][7]);
        }
    }
}

// ---------------- single-block exclusive scan of degrees --------------------
__global__ __launch_bounds__(SCAN_T) void k_scan() {
    __shared__ int sh[SCAN_T];
    int t = threadIdx.x;
    const int CHUNK = (N_NODES + SCAN_T - 1) / SCAN_T;  // 49
    int beg = t * CHUNK;
    int end = beg + CHUNK < N_NODES ? beg + CHUNK : N_NODES;
    int s = 0;
    for (int i = beg; i < end; i++) s += g_cnt[i];
    sh[t] = s;
    __syncthreads();
    for (int o = 1; o < SCAN_T; o <<= 1) {
        int v = (t >= o) ? sh[t - o] : 0;
        __syncthreads();
        sh[t] += v;
        __syncthreads();
    }
    int run = (t > 0) ? sh[t - 1] : 0;
    for (int i = beg; i < end; i++) {
        int c = g_cnt[i];
        g_off[i] = run;
        g_pos[i] = run;
        run += c;
    }
    if (beg < N_NODES && end == N_NODES) g_off[N_NODES] = run;
}

// ---------------- bucket fill: src + bias in CSR (dst-grouped) order ---------
__global__ __launch_bounds__(256) void k_bucket(const int* __restrict__ ei,
                                                const float* __restrict__ ea,
                                                const float* __restrict__ We) {
    int e = blockIdx.x * 256 + threadIdx.x;
    if (e >= N_EDGES) return;
    int src = ei[e];
    int dst = ei[N_EDGES + e];
    float a0 = ea[e * 3 + 0], a1 = ea[e * 3 + 1], a2 = ea[e * 3 + 2];
    float4 b;
    b.x = a0 * We[0] + a1 * We[4] + a2 * We[8];
    b.y = a0 * We[1] + a1 * We[5] + a2 * We[9];
    b.z = a0 * We[2] + a1 * We[6] + a2 * We[10];
    b.w = a0 * We[3] + a1 * We[7] + a2 * We[11];
    int p = atomicAdd(&g_pos[dst], 1);
    g_src[p] = src;
    ((float4*)g_biasS)[p] = b;
}

// ---------------- fused attention + gather: warp per dst node ----------------
// All per-edge streams (g_src, g_biasS) are linear in CSR position: no
// dependent index chain before the K/V row addresses.
__global__ __launch_bounds__(256) void k_gather() {
    int n = blockIdx.x * 8 + (threadIdx.x >> 5);
    if (n >= N_NODES) return;
    int lane = threadIdx.x & 31;
    int h = lane >> 3;                 // head of this lane's float4
    int beg = g_off[n];
    int end = g_off[n + 1];

    float4 q = ((const float4*)(g_Q + (size_t)n * 128))[lane];
    float4 acc = make_float4(0.f, 0.f, 0.f, 0.f);
    float s = 0.f;

    #pragma unroll 2
    for (int i = beg; i < end; i++) {
        int src = g_src[i];                       // linear, bcast
        float bias = g_biasS[i * 4 + h];          // linear, bcast per 8 lanes
        float4 k = ((const float4*)(g_K + (size_t)src * 128))[lane];
        float4 v = ((const float4*)(g_V + (size_t)src * 128))[lane];

        float p = q.x * k.x + q.y * k.y + q.z * k.z + q.w * k.w;
        p += __shfl_xor_sync(0xffffffffu, p, 1);
        p += __shfl_xor_sync(0xffffffffu, p, 2);
        p += __shfl_xor_sync(0xffffffffu, p, 4);   // all 8 lanes have head dot

        float a = p * HD_SCALE + bias;
        a = a >= 0.f ? a : 0.2f * a;               // leaky_relu(0.2)
        // global-max stabilizer cancels in per-(dst,h) normalization;
        // logits O(10) -> exp safe in fp32 (verified R3-R5, rel_err 4e-7)
        float ex = __expf(a);
        s += ex;
        acc.x = fmaf(v.x, ex, acc.x);
        acc.y = fmaf(v.y, ex, acc.y);
        acc.z = fmaf(v.z, ex, acc.z);
        acc.w = fmaf(v.w, ex, acc.w);
    }

    float inv = 1.f / fmaxf(s, 1e-12f);
    float4* o = (float4*)(g_agg + (size_t)n * 128);
    o[lane] = make_float4(acc.x * inv, acc.y * inv, acc.z * inv, acc.w * inv);
}

// ---------------- output GEMM: relu(x@Wm_x + agg@Wf + bf) --------------------
__global__ __launch_bounds__(256) void k_out(const float* __restrict__ x,
                                             const float* __restrict__ Wm,
                                             float* __restrict__ out) {
    int rg = threadIdx.x >> 4;
    int c0 = (threadIdx.x & 15) * 8;
    int r0 = blockIdx.x * 64 + rg * 4;

    int rr[4];
    #pragma unroll
    for (int r = 0; r < 4; r++) {
        int ri = r0 + r;
        rr[r] = ri < N_NODES ? ri : (N_NODES - 1);
    }

    float acc[4][8];
    #pragma unroll
    for (int r = 0; r < 4; r++)
        #pragma unroll
        for (int c = 0; c < 8; c++) acc[r][c] = 0.f;

    #pragma unroll 4
    for (int k = 0; k < 128; k++) {
        float4 w0 = *(const float4*)(Wm + k * 128 + c0);
        float4 w1 = *(const float4*)(Wm + k * 128 + c0 + 4);
        float xv[4];
        #pragma unroll
        for (int r = 0; r < 4; r++) xv[r] = x[(size_t)rr[r] * 128 + k];
        #pragma unroll
        for (int r = 0; r < 4; r++) {
            acc[r][0] = fmaf(xv[r], w0.x, acc[r][0]);
            acc[r][1] = fmaf(xv[r], w0.y, acc[r][1]);
            acc[r][2] = fmaf(xv[r], w0.z, acc[r][2]);
            acc[r][3] = fmaf(xv[r], w0.w, acc[r][3]);
            acc[r][4] = fmaf(xv[r], w1.x, acc[r][4]);
            acc[r][5] = fmaf(xv[r], w1.y, acc[r][5]);
            acc[r][6] = fmaf(xv[r], w1.z, acc[r][6]);
            acc[r][7] = fmaf(xv[r], w1.w, acc[r][7]);
        }
    }

    #pragma unroll 4
    for (int k = 0; k < 128; k++) {
        float4 w0 = *(const float4*)(g_Wf + k * 128 + c0);
        float4 w1 = *(const float4*)(g_Wf + k * 128 + c0 + 4);
        float av[4];
        #pragma unroll
        for (int r = 0; r < 4; r++) av[r] = g_agg[(size_t)rr[r] * 128 + k];
        #pragma unroll
        for (int r = 0; r < 4; r++) {
            acc[r][0] = fmaf(av[r], w0.x, acc[r][0]);
            acc[r][1] = fmaf(av[r], w0.y, acc[r][1]);
            acc[r][2] = fmaf(av[r], w0.z, acc[r][2]);
            acc[r][3] = fmaf(av[r], w0.w, acc[r][3]);
            acc[r][4] = fmaf(av[r], w1.x, acc[r][4]);
            acc[r][5] = fmaf(av[r], w1.y, acc[r][5]);
            acc[r][6] = fmaf(av[r], w1.z, acc[r][6]);
            acc[r][7] = fmaf(av[r], w1.w, acc[r][7]);
        }
    }

    float4 b0 = *(const float4*)(g_bf + c0);
    float4 b1 = *(const float4*)(g_bf + c0 + 4);
    #pragma unroll
    for (int r = 0; r < 4; r++) {
        if (r0 + r < N_NODES) {
            float4* o = (float4*)(out + (size_t)(r0 + r) * 128 + c0);
            o[0] = make_float4(fmaxf(acc[r][0] + b0.x, 0.f), fmaxf(acc[r][1] + b0.y, 0.f),
                               fmaxf(acc[r][2] + b0.z, 0.f), fmaxf(acc[r][3] + b0.w, 0.f));
            o[1] = make_float4(fmaxf(acc[r][4] + b1.x, 0.f), fmaxf(acc[r][5] + b1.y, 0.f),
                               fmaxf(acc[r][6] + b1.z, 0.f), fmaxf(acc[r][7] + b1.w, 0.f));
        }
    }
}

// ---------------- launch ------------------------------------------------------
extern "C" void kernel_launch(void* const* d_in, const int* in_sizes, int n_in,
                              void* d_out, int out_size) {
    const float* x  = (const float*)d_in[0];
    const int*   ei = (const int*)d_in[1];
    const float* ea = (const float*)d_in[2];
    const float* Wq = (const float*)d_in[3];
    const float* Wk = (const float*)d_in[4];
    const float* Wv = (const float*)d_in[5];
    const float* We = (const float*)d_in[6];
    const float* Wo = (const float*)d_in[7];
    const float* bo = (const float*)d_in[8];
    const float* Wm = (const float*)d_in[9];
    const float* bm = (const float*)d_in[10];
    float* out = (float*)d_out;

    k_init<<<(N_NODES + 255) / 256, 256>>>();
    k_hist<<<(N_EDGES + 255) / 256, 256>>>(ei);
    k_scan<<<1, SCAN_T>>>();
    k_bucket<<<(N_EDGES + 255) / 256, 256>>>(ei, ea, We);
    k_fusew<<<128, 128>>>(Wo, Wm, bo, bm);
    k_qkv<<<dim3((N_NODES + 63) / 64, 3), 256>>>(x, Wq, Wk, Wv);
    k_gather<<<(N_NODES + 7) / 8, 256>>>();
    k_out<<<(N_NODES + 63) / 64, 256>>>(x, Wm, out);
}

// round 8
// speedup vs baseline: 1.4905x; 1.2641x over previous
#include <cuda_runtime.h>
#include <cuda_bf16.h>
#include <cstdint>

#define N_NODES 50000
#define N_EDGES 800000
#define HD_SCALE 0.17677669529663687f   // 1/sqrt(32)
#define SCAN_T 1024
#define KP 136                           // padded bf16 row stride (272B)

// ---------------- scratch (device globals: no allocation allowed) ----------
__device__ __align__(256) float g_Q[N_NODES * 128];
__device__ __align__(256) float g_K[N_NODES * 128];
__device__ __align__(256) float g_V[N_NODES * 128];
__device__ __align__(256) float g_biasS[N_EDGES * 4];
__device__ __align__(256) float g_agg[N_NODES * 128];
__device__ __align__(256) float g_Wf[128 * 128];
__device__ __align__(256) float g_bf[128];
__device__ __align__(256) int   g_cnt[N_NODES];
__device__ __align__(256) int   g_off[N_NODES + 1];
__device__ __align__(256) int   g_pos[N_NODES];
__device__ __align__(256) int   g_src[N_EDGES];

// ---------------- mma.sync helpers (arch-neutral PTX, sm_80+) ---------------
__device__ __forceinline__ uint32_t smem_u32(const void* p) {
    uint32_t a;
    asm("{ .reg .u64 t; cvta.to.shared.u64 t, %1; cvt.u32.u64 %0, t; }"
        : "=r"(a) : "l"(p));
    return a;
}
#define LDM_X4(r, addr)                                                        \
    asm volatile("ldmatrix.sync.aligned.m8n8.x4.shared.b16 {%0,%1,%2,%3}, [%4];" \
                 : "=r"((r)[0]), "=r"((r)[1]), "=r"((r)[2]), "=r"((r)[3])      \
                 : "r"(addr))
#define MMA_B16(c, a, b0, b1)                                                  \
    asm volatile("mma.sync.aligned.m16n8k16.row.col.f32.bf16.bf16.f32 "        \
                 "{%0,%1,%2,%3}, {%4,%5,%6,%7}, {%8,%9}, {%0,%1,%2,%3};"       \
                 : "+f"((c)[0]), "+f"((c)[1]), "+f"((c)[2]), "+f"((c)[3])      \
                 : "r"((a)[0]), "r"((a)[1]), "r"((a)[2]), "r"((a)[3]),         \
                   "r"(b0), "r"(b1))

// smem layout (bytes within dynamic smem); each tile 128 x KP bf16
#define T_BYTES (128 * KP * 2)          // 34816
#define SM_AH 0
#define SM_AL (SM_AH + T_BYTES)
#define SM_BH (SM_AL + T_BYTES)
#define SM_BL (SM_BH + T_BYTES)
#define SM_MMA_TOT (SM_BL + T_BYTES)    // 139264

__device__ __forceinline__ void split_store(char* hb, char* lb, int row, int col,
                                            float v) {
    __nv_bfloat16 hi = __float2bfloat16(v);
    __nv_bfloat16 lo = __float2bfloat16(v - __bfloat162float(hi));
    int off = (row * KP + col) * 2;
    *(__nv_bfloat16*)(hb + off) = hi;
    *(__nv_bfloat16*)(lb + off) = lo;
}

// Load A tile (128 rows of src starting at r0, row-clamped) split hi/lo.
__device__ __forceinline__ void load_A(char* sm, const float* __restrict__ src,
                                       int r0, int tid) {
    for (int i = tid; i < 128 * 32; i += 256) {
        int r = i >> 5, c = (i & 31) * 4;
        int gr = r0 + r; if (gr >= N_NODES) gr = N_NODES - 1;
        float4 v = *(const float4*)(src + (size_t)gr * 128 + c);
        split_store(sm + SM_AH, sm + SM_AL, r, c + 0, v.x);
        split_store(sm + SM_AH, sm + SM_AL, r, c + 1, v.y);
        split_store(sm + SM_AH, sm + SM_AL, r, c + 2, v.z);
        split_store(sm + SM_AH, sm + SM_AL, r, c + 3, v.w);
    }
}
// Load B tile as n-major (row n holds 128 k-values): W is k x n row-major.
__device__ __forceinline__ void load_B(char* sm, const float* __restrict__ W,
                                       int tid) {
    for (int i = tid; i < 128 * 32; i += 256) {
        int k = i >> 5, n0 = (i & 31) * 4;
        float4 v = *(const float4*)(W + k * 128 + n0);
        split_store(sm + SM_BH, sm + SM_BL, n0 + 0, k, v.x);
        split_store(sm + SM_BH, sm + SM_BL, n0 + 1, k, v.y);
        split_store(sm + SM_BH, sm + SM_BL, n0 + 2, k, v.z);
        split_store(sm + SM_BH, sm + SM_BL, n0 + 3, k, v.w);
    }
}

// One K=128 accumulation sweep over the staged tiles.
__device__ __forceinline__ void mma_sweep(uint32_t smb, int lane, int mB, int nB,
                                          float acc[2][8][4]) {
    int aRow = lane & 15;
    int aKH  = (lane >> 4) * 8;
    int bRow = (lane & 7) + ((lane >> 4) << 3);
    int bKH  = ((lane >> 3) & 1) * 8;
    #pragma unroll
    for (int ks = 0; ks < 8; ks++) {
        int k0 = ks * 16;
        uint32_t ah[2][4], al[2][4], bh[4][4], bl[4][4];
        #pragma unroll
        for (int mt = 0; mt < 2; mt++) {
            uint32_t off = (uint32_t)((mB + mt * 16 + aRow) * KP + k0 + aKH) * 2;
            LDM_X4(ah[mt], smb + SM_AH + off);
            LDM_X4(al[mt], smb + SM_AL + off);
        }
        #pragma unroll
        for (int p = 0; p < 4; p++) {
            uint32_t off = (uint32_t)((nB + p * 16 + bRow) * KP + k0 + bKH) * 2;
            LDM_X4(bh[p], smb + SM_BH + off);
            LDM_X4(bl[p], smb + SM_BL + off);
        }
        #pragma unroll
        for (int mt = 0; mt < 2; mt++)
            #pragma unroll
            for (int nt = 0; nt < 8; nt++) {
                int p = nt >> 1, q = (nt & 1) * 2;
                MMA_B16(acc[mt][nt], ah[mt], bh[p][q], bh[p][q + 1]);
                MMA_B16(acc[mt][nt], ah[mt], bl[p][q], bl[p][q + 1]);
                MMA_B16(acc[mt][nt], al[mt], bh[p][q], bh[p][q + 1]);
            }
    }
}

// ---------------- QKV GEMM on mma.sync ---------------------------------------
__global__ __launch_bounds__(256) void k_qkv_mma(const float* __restrict__ x,
                                                 const float* __restrict__ Wq,
                                                 const float* __restrict__ Wk,
                                                 const float* __restrict__ Wv) {
    extern __shared__ char sm[];
    int tid = threadIdx.x, lane = tid & 31, w = tid >> 5;
    int mB = (w >> 1) * 32, nB = (w & 1) * 64;
    int r0 = blockIdx.x * 128;

    const float* W;
    float* out;
    if (blockIdx.y == 0)      { W = Wq; out = g_Q; }
    else if (blockIdx.y == 1) { W = Wk; out = g_K; }
    else                      { W = Wv; out = g_V; }

    load_A(sm, x, r0, tid);
    load_B(sm, W, tid);
    __syncthreads();

    float acc[2][8][4];
    #pragma unroll
    for (int mt = 0; mt < 2; mt++)
        #pragma unroll
        for (int nt = 0; nt < 8; nt++)
            #pragma unroll
            for (int i = 0; i < 4; i++) acc[mt][nt][i] = 0.f;

    mma_sweep(smem_u32(sm), lane, mB, nB, acc);

    int gq = lane >> 2, tq = lane & 3;
    #pragma unroll
    for (int mt = 0; mt < 2; mt++)
        #pragma unroll
        for (int nt = 0; nt < 8; nt++) {
            int col = nB + nt * 8 + tq * 2;
            int row0 = r0 + mB + mt * 16 + gq;
            if (row0 < N_NODES)
                *(float2*)(out + (size_t)row0 * 128 + col) =
                    make_float2(acc[mt][nt][0], acc[mt][nt][1]);
            int row1 = row0 + 8;
            if (row1 < N_NODES)
                *(float2*)(out + (size_t)row1 * 128 + col) =
                    make_float2(acc[mt][nt][2], acc[mt][nt][3]);
        }
}

// ---------------- output GEMM on mma.sync: relu(x@Wm_x + agg@Wf + bf) --------
__global__ __launch_bounds__(256) void k_out_mma(const float* __restrict__ x,
                                                 const float* __restrict__ Wm,
                                                 float* __restrict__ out) {
    extern __shared__ char sm[];
    int tid = threadIdx.x, lane = tid & 31, w = tid >> 5;
    int mB = (w >> 1) * 32, nB = (w & 1) * 64;
    int r0 = blockIdx.x * 128;
    uint32_t smb = smem_u32(sm);

    float acc[2][8][4];
    #pragma unroll
    for (int mt = 0; mt < 2; mt++)
        #pragma unroll
        for (int nt = 0; nt < 8; nt++)
            #pragma unroll
            for (int i = 0; i < 4; i++) acc[mt][nt][i] = 0.f;

    #pragma unroll
    for (int pass = 0; pass < 2; pass++) {
        const float* A = pass ? (const float*)g_agg : x;
        const float* B = pass ? (const float*)g_Wf : Wm;   // Wm rows 0-127 = x part
        __syncthreads();
        load_A(sm, A, r0, tid);
        load_B(sm, B, tid);
        __syncthreads();
        mma_sweep(smb, lane, mB, nB, acc);
    }

    int gq = lane >> 2, tq = lane & 3;
    #pragma unroll
    for (int mt = 0; mt < 2; mt++)
        #pragma unroll
        for (int nt = 0; nt < 8; nt++) {
            int col = nB + nt * 8 + tq * 2;
            float b0 = g_bf[col], b1 = g_bf[col + 1];
            int row0 = r0 + mB + mt * 16 + gq;
            if (row0 < N_NODES)
                *(float2*)(out + (size_t)row0 * 128 + col) =
                    make_float2(fmaxf(acc[mt][nt][0] + b0, 0.f),
                                fmaxf(acc[mt][nt][1] + b1, 0.f));
            int row1 = row0 + 8;
            if (row1 < N_NODES)
                *(float2*)(out + (size_t)row1 * 128 + col) =
                    make_float2(fmaxf(acc[mt][nt][2] + b0, 0.f),
                                fmaxf(acc[mt][nt][3] + b1, 0.f));
        }
}

// ---------------- init / hist / scan / bucket / fusew / gather (R6) ----------
__global__ void k_init() {
    int i = blockIdx.x * 256 + threadIdx.x;
    if (i < N_NODES) g_cnt[i] = 0;
}

__global__ __launch_bounds__(256) void k_hist(const int* __restrict__ ei) {
    int e = blockIdx.x * 256 + threadIdx.x;
    if (e >= N_EDGES) return;
    atomicAdd(&g_cnt[ei[N_EDGES + e]], 1);
}

__global__ void k_fusew(const float* __restrict__ Wo, const float* __restrict__ Wm,
                        const float* __restrict__ bo, const float* __restrict__ bm) {
    int r = blockIdx.x, j = threadIdx.x;
    float acc = 0.f;
    #pragma unroll 8
    for (int k = 0; k < 128; k++)
        acc += Wo[r * 128 + k] * Wm[(128 + k) * 128 + j];
    g_Wf[r * 128 + j] = acc;
    if (r == 0) {
        float b = bm[j];
        #pragma unroll 8
        for (int k = 0; k < 128; k++)
            b += bo[k] * Wm[(128 + k) * 128 + j];
        g_bf[j] = b;
    }
}

__global__ __launch_bounds__(SCAN_T) void k_scan() {
    __shared__ int sh[SCAN_T];
    int t = threadIdx.x;
    const int CHUNK = (N_NODES + SCAN_T - 1) / SCAN_T;
    int beg = t * CHUNK;
    int end = beg + CHUNK < N_NODES ? beg + CHUNK : N_NODES;
    int s = 0;
    for (int i = beg; i < end; i++) s += g_cnt[i];
    sh[t] = s;
    __syncthreads();
    for (int o = 1; o < SCAN_T; o <<= 1) {
        int v = (t >= o) ? sh[t - o] : 0;
        __syncthreads();
        sh[t] += v;
        __syncthreads();
    }
    int run = (t > 0) ? sh[t - 1] : 0;
    for (int i = beg; i < end; i++) {
        int c = g_cnt[i];
        g_off[i] = run;
        g_pos[i] = run;
        run += c;
    }
    if (beg < N_NODES && end == N_NODES) g_off[N_NODES] = run;
}

__global__ __launch_bounds__(256) void k_bucket(const int* __restrict__ ei,
                                                const float* __restrict__ ea,
                                                const float* __restrict__ We) {
    int e = blockIdx.x * 256 + threadIdx.x;
    if (e >= N_EDGES) return;
    int src = ei[e];
    int dst = ei[N_EDGES + e];
    float a0 = ea[e * 3 + 0], a1 = ea[e * 3 + 1], a2 = ea[e * 3 + 2];
    float4 b;
    b.x = a0 * We[0] + a1 * We[4] + a2 * We[8];
    b.y = a0 * We[1] + a1 * We[5] + a2 * We[9];
    b.z = a0 * We[2] + a1 * We[6] + a2 * We[10];
    b.w = a0 * We[3] + a1 * We[7] + a2 * We[11];
    int p = atomicAdd(&g_pos[dst], 1);
    g_src[p] = src;
    ((float4*)g_biasS)[p] = b;
}

__global__ __launch_bounds__(256) void k_gather() {
    int n = blockIdx.x * 8 + (threadIdx.x >> 5);
    if (n >= N_NODES) return;
    int lane = threadIdx.x & 31;
    int h = lane >> 3;
    int beg = g_off[n];
    int end = g_off[n + 1];

    float4 q = ((const float4*)(g_Q + (size_t)n * 128))[lane];
    float4 acc = make_float4(0.f, 0.f, 0.f, 0.f);
    float s = 0.f;

    #pragma unroll 2
    for (int i = beg; i < end; i++) {
        int src = g_src[i];
        float bias = g_biasS[i * 4 + h];
        float4 k = ((const float4*)(g_K + (size_t)src * 128))[lane];
        float4 v = ((const float4*)(g_V + (size_t)src * 128))[lane];

        float p = q.x * k.x + q.y * k.y + q.z * k.z + q.w * k.w;
        p += __shfl_xor_sync(0xffffffffu, p, 1);
        p += __shfl_xor_sync(0xffffffffu, p, 2);
        p += __shfl_xor_sync(0xffffffffu, p, 4);

        float a = p * HD_SCALE + bias;
        a = a >= 0.f ? a : 0.2f * a;
        float ex = __expf(a);
        s += ex;
        acc.x = fmaf(v.x, ex, acc.x);
        acc.y = fmaf(v.y, ex, acc.y);
        acc.z = fmaf(v.z, ex, acc.z);
        acc.w = fmaf(v.w, ex, acc.w);
    }

    float inv = 1.f / fmaxf(s, 1e-12f);
    float4* o = (float4*)(g_agg + (size_t)n * 128);
    o[lane] = make_float4(acc.x * inv, acc.y * inv, acc.z * inv, acc.w * inv);
}

// ---------------- launch ------------------------------------------------------
extern "C" void kernel_launch(void* const* d_in, const int* in_sizes, int n_in,
                              void* d_out, int out_size) {
    const float* x  = (const float*)d_in[0];
    const int*   ei = (const int*)d_in[1];
    const float* ea = (const float*)d_in[2];
    const float* Wq = (const float*)d_in[3];
    const float* Wk = (const float*)d_in[4];
    const float* Wv = (const float*)d_in[5];
    const float* We = (const float*)d_in[6];
    const float* Wo = (const float*)d_in[7];
    const float* bo = (const float*)d_in[8];
    const float* Wm = (const float*)d_in[9];
    const float* bm = (const float*)d_in[10];
    float* out = (float*)d_out;

    static bool attr_done = false;
    if (!attr_done) {
        cudaFuncSetAttribute(k_qkv_mma, cudaFuncAttributeMaxDynamicSharedMemorySize,
                             SM_MMA_TOT);
        cudaFuncSetAttribute(k_out_mma, cudaFuncAttributeMaxDynamicSharedMemorySize,
                             SM_MMA_TOT);
        attr_done = true;
    }

    k_init<<<(N_NODES + 255) / 256, 256>>>();
    k_hist<<<(N_EDGES + 255) / 256, 256>>>(ei);
    k_scan<<<1, SCAN_T>>>();
    k_bucket<<<(N_EDGES + 255) / 256, 256>>>(ei, ea, We);
    k_fusew<<<128, 128>>>(Wo, Wm, bo, bm);
    k_qkv_mma<<<dim3((N_NODES + 127) / 128, 3), 256, SM_MMA_TOT>>>(x, Wq, Wk, Wv);
    k_gather<<<(N_NODES + 7) / 8, 256>>>();
    k_out_mma<<<(N_NODES + 127) / 128, 256, SM_MMA_TOT>>>(x, Wm, out);
}

// round 9
// speedup vs baseline: 1.5153x; 1.0167x over previous
#include <cuda_runtime.h>
#include <cuda_bf16.h>
#include <cstdint>

#define N_NODES 50000
#define N_EDGES 800000
#define HD_SCALE 0.17677669529663687f   // 1/sqrt(32)
#define SCAN_T 1024
#define KP 136                           // padded bf16 row stride (272B)

// ---------------- scratch (device globals: no allocation allowed) ----------
__device__ __align__(256) float g_Q[N_NODES * 128];
__device__ __align__(256) float g_K[N_NODES * 128];
__device__ __align__(256) float g_V[N_NODES * 128];
__device__ __align__(256) float g_biasS[N_EDGES * 4];
__device__ __align__(256) float g_agg[N_NODES * 128];
__device__ __align__(256) float g_Wf[128 * 128];
__device__ __align__(256) float g_bf[128];
__device__ __align__(256) int   g_cnt[N_NODES];
__device__ __align__(256) int   g_off[N_NODES + 1];
__device__ __align__(256) int   g_pos[N_NODES];
__device__ __align__(256) int   g_src[N_EDGES];

// ---------------- mma.sync helpers (arch-neutral PTX, sm_80+) ---------------
__device__ __forceinline__ uint32_t smem_u32(const void* p) {
    uint32_t a;
    asm("{ .reg .u64 t; cvta.to.shared.u64 t, %1; cvt.u32.u64 %0, t; }"
        : "=r"(a) : "l"(p));
    return a;
}
#define LDM_X4(r, addr)                                                        \
    asm volatile("ldmatrix.sync.aligned.m8n8.x4.shared.b16 {%0,%1,%2,%3}, [%4];" \
                 : "=r"((r)[0]), "=r"((r)[1]), "=r"((r)[2]), "=r"((r)[3])      \
                 : "r"(addr))
#define MMA_B16(c, a, b0, b1)                                                  \
    asm volatile("mma.sync.aligned.m16n8k16.row.col.f32.bf16.bf16.f32 "        \
                 "{%0,%1,%2,%3}, {%4,%5,%6,%7}, {%8,%9}, {%0,%1,%2,%3};"       \
                 : "+f"((c)[0]), "+f"((c)[1]), "+f"((c)[2]), "+f"((c)[3])      \
                 : "r"((a)[0]), "r"((a)[1]), "r"((a)[2]), "r"((a)[3]),         \
                   "r"(b0), "r"(b1))

// smem layout (bytes within dynamic smem); each tile 128 x KP bf16
#define T_BYTES (128 * KP * 2)          // 34816
#define SM_AH 0
#define SM_AL (SM_AH + T_BYTES)
#define SM_BH (SM_AL + T_BYTES)
#define SM_BL (SM_BH + T_BYTES)
#define SM_MMA_TOT (SM_BL + T_BYTES)    // 139264

__device__ __forceinline__ void split_store(char* hb, char* lb, int row, int col,
                                            float v) {
    __nv_bfloat16 hi = __float2bfloat16(v);
    __nv_bfloat16 lo = __float2bfloat16(v - __bfloat162float(hi));
    int off = (row * KP + col) * 2;
    *(__nv_bfloat16*)(hb + off) = hi;
    *(__nv_bfloat16*)(lb + off) = lo;
}

__device__ __forceinline__ void load_A(char* sm, const float* __restrict__ src,
                                       int r0, int tid) {
    for (int i = tid; i < 128 * 32; i += 256) {
        int r = i >> 5, c = (i & 31) * 4;
        int gr = r0 + r; if (gr >= N_NODES) gr = N_NODES - 1;
        float4 v = *(const float4*)(src + (size_t)gr * 128 + c);
        split_store(sm + SM_AH, sm + SM_AL, r, c + 0, v.x);
        split_store(sm + SM_AH, sm + SM_AL, r, c + 1, v.y);
        split_store(sm + SM_AH, sm + SM_AL, r, c + 2, v.z);
        split_store(sm + SM_AH, sm + SM_AL, r, c + 3, v.w);
    }
}
__device__ __forceinline__ void load_B(char* sm, const float* __restrict__ W,
                                       int tid) {
    for (int i = tid; i < 128 * 32; i += 256) {
        int k = i >> 5, n0 = (i & 31) * 4;
        float4 v = *(const float4*)(W + k * 128 + n0);
        split_store(sm + SM_BH, sm + SM_BL, n0 + 0, k, v.x);
        split_store(sm + SM_BH, sm + SM_BL, n0 + 1, k, v.y);
        split_store(sm + SM_BH, sm + SM_BL, n0 + 2, k, v.z);
        split_store(sm + SM_BH, sm + SM_BL, n0 + 3, k, v.w);
    }
}

__device__ __forceinline__ void mma_sweep(uint32_t smb, int lane, int mB, int nB,
                                          float acc[2][8][4]) {
    int aRow = lane & 15;
    int aKH  = (lane >> 4) * 8;
    int bRow = (lane & 7) + ((lane >> 4) << 3);
    int bKH  = ((lane >> 3) & 1) * 8;
    #pragma unroll
    for (int ks = 0; ks < 8; ks++) {
        int k0 = ks * 16;
        uint32_t ah[2][4], al[2][4], bh[4][4], bl[4][4];
        #pragma unroll
        for (int mt = 0; mt < 2; mt++) {
            uint32_t off = (uint32_t)((mB + mt * 16 + aRow) * KP + k0 + aKH) * 2;
            LDM_X4(ah[mt], smb + SM_AH + off);
            LDM_X4(al[mt], smb + SM_AL + off);
        }
        #pragma unroll
        for (int p = 0; p < 4; p++) {
            uint32_t off = (uint32_t)((nB + p * 16 + bRow) * KP + k0 + bKH) * 2;
            LDM_X4(bh[p], smb + SM_BH + off);
            LDM_X4(bl[p], smb + SM_BL + off);
        }
        #pragma unroll
        for (int mt = 0; mt < 2; mt++)
            #pragma unroll
            for (int nt = 0; nt < 8; nt++) {
                int p = nt >> 1, q = (nt & 1) * 2;
                MMA_B16(acc[mt][nt], ah[mt], bh[p][q], bh[p][q + 1]);
                MMA_B16(acc[mt][nt], ah[mt], bl[p][q], bl[p][q + 1]);
                MMA_B16(acc[mt][nt], al[mt], bh[p][q], bh[p][q + 1]);
            }
    }
}

// ---------------- QKV GEMM on mma.sync ---------------------------------------
__global__ __launch_bounds__(256) void k_qkv_mma(const float* __restrict__ x,
                                                 const float* __restrict__ Wq,
                                                 const float* __restrict__ Wk,
                                                 const float* __restrict__ Wv) {
    extern __shared__ char sm[];
    int tid = threadIdx.x, lane = tid & 31, w = tid >> 5;
    int mB = (w >> 1) * 32, nB = (w & 1) * 64;
    int r0 = blockIdx.x * 128;

    const float* W;
    float* out;
    if (blockIdx.y == 0)      { W = Wq; out = g_Q; }
    else if (blockIdx.y == 1) { W = Wk; out = g_K; }
    else                      { W = Wv; out = g_V; }

    load_A(sm, x, r0, tid);
    load_B(sm, W, tid);
    __syncthreads();

    float acc[2][8][4];
    #pragma unroll
    for (int mt = 0; mt < 2; mt++)
        #pragma unroll
        for (int nt = 0; nt < 8; nt++)
            #pragma unroll
            for (int i = 0; i < 4; i++) acc[mt][nt][i] = 0.f;

    mma_sweep(smem_u32(sm), lane, mB, nB, acc);

    int gq = lane >> 2, tq = lane & 3;
    #pragma unroll
    for (int mt = 0; mt < 2; mt++)
        #pragma unroll
        for (int nt = 0; nt < 8; nt++) {
            int col = nB + nt * 8 + tq * 2;
            int row0 = r0 + mB + mt * 16 + gq;
            if (row0 < N_NODES)
                *(float2*)(out + (size_t)row0 * 128 + col) =
                    make_float2(acc[mt][nt][0], acc[mt][nt][1]);
            int row1 = row0 + 8;
            if (row1 < N_NODES)
                *(float2*)(out + (size_t)row1 * 128 + col) =
                    make_float2(acc[mt][nt][2], acc[mt][nt][3]);
        }
}

// ---------------- output GEMM on mma.sync: relu(x@Wm_x + agg@Wf + bf) --------
__global__ __launch_bounds__(256) void k_out_mma(const float* __restrict__ x,
                                                 const float* __restrict__ Wm,
                                                 float* __restrict__ out) {
    extern __shared__ char sm[];
    int tid = threadIdx.x, lane = tid & 31, w = tid >> 5;
    int mB = (w >> 1) * 32, nB = (w & 1) * 64;
    int r0 = blockIdx.x * 128;
    uint32_t smb = smem_u32(sm);

    float acc[2][8][4];
    #pragma unroll
    for (int mt = 0; mt < 2; mt++)
        #pragma unroll
        for (int nt = 0; nt < 8; nt++)
            #pragma unroll
            for (int i = 0; i < 4; i++) acc[mt][nt][i] = 0.f;

    #pragma unroll
    for (int pass = 0; pass < 2; pass++) {
        const float* A = pass ? (const float*)g_agg : x;
        const float* B = pass ? (const float*)g_Wf : Wm;
        __syncthreads();
        load_A(sm, A, r0, tid);
        load_B(sm, B, tid);
        __syncthreads();
        mma_sweep(smb, lane, mB, nB, acc);
    }

    int gq = lane >> 2, tq = lane & 3;
    #pragma unroll
    for (int mt = 0; mt < 2; mt++)
        #pragma unroll
        for (int nt = 0; nt < 8; nt++) {
            int col = nB + nt * 8 + tq * 2;
            float b0 = g_bf[col], b1 = g_bf[col + 1];
            int row0 = r0 + mB + mt * 16 + gq;
            if (row0 < N_NODES)
                *(float2*)(out + (size_t)row0 * 128 + col) =
                    make_float2(fmaxf(acc[mt][nt][0] + b0, 0.f),
                                fmaxf(acc[mt][nt][1] + b1, 0.f));
            int row1 = row0 + 8;
            if (row1 < N_NODES)
                *(float2*)(out + (size_t)row1 * 128 + col) =
                    make_float2(fmaxf(acc[mt][nt][2] + b0, 0.f),
                                fmaxf(acc[mt][nt][3] + b1, 0.f));
        }
}

// ---------------- init / hist / scan / bucket / fusew ------------------------
__global__ void k_init() {
    int i = blockIdx.x * 256 + threadIdx.x;
    if (i < N_NODES) g_cnt[i] = 0;
}

__global__ __launch_bounds__(256) void k_hist(const int* __restrict__ ei) {
    int e = blockIdx.x * 256 + threadIdx.x;
    if (e >= N_EDGES) return;
    atomicAdd(&g_cnt[ei[N_EDGES + e]], 1);
}

__global__ void k_fusew(const float* __restrict__ Wo, const float* __restrict__ Wm,
                        const float* __restrict__ bo, const float* __restrict__ bm) {
    int r = blockIdx.x, j = threadIdx.x;
    float acc = 0.f;
    #pragma unroll 8
    for (int k = 0; k < 128; k++)
        acc += Wo[r * 128 + k] * Wm[(128 + k) * 128 + j];
    g_Wf[r * 128 + j] = acc;
    if (r == 0) {
        float b = bm[j];
        #pragma unroll 8
        for (int k = 0; k < 128; k++)
            b += bo[k] * Wm[(128 + k) * 128 + j];
        g_bf[j] = b;
    }
}

__global__ __launch_bounds__(SCAN_T) void k_scan() {
    __shared__ int sh[SCAN_T];
    int t = threadIdx.x;
    const int CHUNK = (N_NODES + SCAN_T - 1) / SCAN_T;
    int beg = t * CHUNK;
    int end = beg + CHUNK < N_NODES ? beg + CHUNK : N_NODES;
    int s = 0;
    for (int i = beg; i < end; i++) s += g_cnt[i];
    sh[t] = s;
    __syncthreads();
    for (int o = 1; o < SCAN_T; o <<= 1) {
        int v = (t >= o) ? sh[t - o] : 0;
        __syncthreads();
        sh[t] += v;
        __syncthreads();
    }
    int run = (t > 0) ? sh[t - 1] : 0;
    for (int i = beg; i < end; i++) {
        int c = g_cnt[i];
        g_off[i] = run;
        g_pos[i] = run;
        run += c;
    }
    if (beg < N_NODES && end == N_NODES) g_off[N_NODES] = run;
}

__global__ __launch_bounds__(256) void k_bucket(const int* __restrict__ ei,
                                                const float* __restrict__ ea,
                                                const float* __restrict__ We) {
    int e = blockIdx.x * 256 + threadIdx.x;
    if (e >= N_EDGES) return;
    int src = ei[e];
    int dst = ei[N_EDGES + e];
    float a0 = ea[e * 3 + 0], a1 = ea[e * 3 + 1], a2 = ea[e * 3 + 2];
    float4 b;
    b.x = a0 * We[0] + a1 * We[4] + a2 * We[8];
    b.y = a0 * We[1] + a1 * We[5] + a2 * We[9];
    b.z = a0 * We[2] + a1 * We[6] + a2 * We[10];
    b.w = a0 * We[3] + a1 * We[7] + a2 * We[11];
    int p = atomicAdd(&g_pos[dst], 1);
    g_src[p] = src;
    ((float4*)g_biasS)[p] = b;
}

// ---------------- fused attention + gather: warp/node, 4-edge pipeline -------
__global__ __launch_bounds__(256) void k_gather() {
    int n = blockIdx.x * 8 + (threadIdx.x >> 5);
    if (n >= N_NODES) return;
    int lane = threadIdx.x & 31;
    int h = lane >> 3;
    int beg = g_off[n];
    int end = g_off[n + 1];

    float4 q = ((const float4*)(g_Q + (size_t)n * 128))[lane];
    float4 acc = make_float4(0.f, 0.f, 0.f, 0.f);
    float s = 0.f;

    int i = beg;
    // 4-edge groups: batch all loads (8 float4 + 4 int + 4 float, independent)
    // before any dependent shfl/exp work -> MLP ~8 per lane.
    for (; i + 4 <= end; i += 4) {
        int   srcq[4];
        float biasq[4];
        #pragma unroll
        for (int j = 0; j < 4; j++) {
            srcq[j]  = g_src[i + j];
            biasq[j] = g_biasS[(i + j) * 4 + h];
        }
        float4 kq[4], vq[4];
        #pragma unroll
        for (int j = 0; j < 4; j++) {
            kq[j] = ((const float4*)(g_K + (size_t)srcq[j] * 128))[lane];
            vq[j] = ((const float4*)(g_V + (size_t)srcq[j] * 128))[lane];
        }
        float p[4];
        #pragma unroll
        for (int j = 0; j < 4; j++)
            p[j] = q.x * kq[j].x + q.y * kq[j].y + q.z * kq[j].z + q.w * kq[j].w;
        // 4 independent shfl-reduce chains interleave in the scheduler
        #pragma unroll
        for (int j = 0; j < 4; j++) p[j] += __shfl_xor_sync(0xffffffffu, p[j], 1);
        #pragma unroll
        for (int j = 0; j < 4; j++) p[j] += __shfl_xor_sync(0xffffffffu, p[j], 2);
        #pragma unroll
        for (int j = 0; j < 4; j++) p[j] += __shfl_xor_sync(0xffffffffu, p[j], 4);
        #pragma unroll
        for (int j = 0; j < 4; j++) {
            float a = p[j] * HD_SCALE + biasq[j];
            a = a >= 0.f ? a : 0.2f * a;            // leaky_relu(0.2)
            float ex = __expf(a);                   // global max cancels (R3-R8)
            s += ex;
            acc.x = fmaf(vq[j].x, ex, acc.x);
            acc.y = fmaf(vq[j].y, ex, acc.y);
            acc.z = fmaf(vq[j].z, ex, acc.z);
            acc.w = fmaf(vq[j].w, ex, acc.w);
        }
    }
    // remainder
    for (; i < end; i++) {
        int src = g_src[i];
        float bias = g_biasS[i * 4 + h];
        float4 k = ((const float4*)(g_K + (size_t)src * 128))[lane];
        float4 v = ((const float4*)(g_V + (size_t)src * 128))[lane];
        float p = q.x * k.x + q.y * k.y + q.z * k.z + q.w * k.w;
        p += __shfl_xor_sync(0xffffffffu, p, 1);
        p += __shfl_xor_sync(0xffffffffu, p, 2);
        p += __shfl_xor_sync(0xffffffffu, p, 4);
        float a = p * HD_SCALE + bias;
        a = a >= 0.f ? a : 0.2f * a;
        float ex = __expf(a);
        s += ex;
        acc.x = fmaf(v.x, ex, acc.x);
        acc.y = fmaf(v.y, ex, acc.y);
        acc.z = fmaf(v.z, ex, acc.z);
        acc.w = fmaf(v.w, ex, acc.w);
    }

    float inv = 1.f / fmaxf(s, 1e-12f);
    float4* o = (float4*)(g_agg + (size_t)n * 128);
    o[lane] = make_float4(acc.x * inv, acc.y * inv, acc.z * inv, acc.w * inv);
}

// ---------------- launch ------------------------------------------------------
extern "C" void kernel_launch(void* const* d_in, const int* in_sizes, int n_in,
                              void* d_out, int out_size) {
    const float* x  = (const float*)d_in[0];
    const int*   ei = (const int*)d_in[1];
    const float* ea = (const float*)d_in[2];
    const float* Wq = (const float*)d_in[3];
    const float* Wk = (const float*)d_in[4];
    const float* Wv = (const float*)d_in[5];
    const float* We = (const float*)d_in[6];
    const float* Wo = (const float*)d_in[7];
    const float* bo = (const float*)d_in[8];
    const float* Wm = (const float*)d_in[9];
    const float* bm = (const float*)d_in[10];
    float* out = (float*)d_out;

    static bool attr_done = false;
    if (!attr_done) {
        cudaFuncSetAttribute(k_qkv_mma, cudaFuncAttributeMaxDynamicSharedMemorySize,
                             SM_MMA_TOT);
        cudaFuncSetAttribute(k_out_mma, cudaFuncAttributeMaxDynamicSharedMemorySize,
                             SM_MMA_TOT);
        attr_done = true;
    }

    k_init<<<(N_NODES + 255) / 256, 256>>>();
    k_hist<<<(N_EDGES + 255) / 256, 256>>>(ei);
    k_scan<<<1, SCAN_T>>>();
    k_bucket<<<(N_EDGES + 255) / 256, 256>>>(ei, ea, We);
    k_fusew<<<128, 128>>>(Wo, Wm, bo, bm);
    k_qkv_mma<<<dim3((N_NODES + 127) / 128, 3), 256, SM_MMA_TOT>>>(x, Wq, Wk, Wv);
    k_gather<<<(N_NODES + 7) / 8, 256>>>();
    k_out_mma<<<(N_NODES + 127) / 128, 256, SM_MMA_TOT>>>(x, Wm, out);
}

// round 10
// speedup vs baseline: 1.5465x; 1.0205x over previous
#include <cuda_runtime.h>
#include <cuda_bf16.h>
#include <cstdint>

#define N_NODES 50000
#define N_EDGES 800000
#define HD_SCALE 0.17677669529663687f   // 1/sqrt(32)
#define SCAN_T 1024
#define KP 136                           // padded bf16 row stride (272B)

// ---------------- scratch (device globals: no allocation allowed) ----------
__device__ __align__(256) float g_Q[N_NODES * 128];
__device__ __align__(256) float g_K[N_NODES * 128];
__device__ __align__(256) float g_V[N_NODES * 128];
__device__ __align__(256) float g_biasS[N_EDGES * 4];
__device__ __align__(256) float g_agg[N_NODES * 128];
__device__ __align__(256) float g_Wf[128 * 128];
__device__ __align__(256) float g_bf[128];
__device__ __align__(256) int   g_cnt[N_NODES];
__device__ __align__(256) int   g_off[N_NODES + 1];
__device__ __align__(256) int   g_pos[N_NODES];
__device__ __align__(256) int   g_src[N_EDGES];

// ---------------- mma.sync helpers (arch-neutral PTX, sm_80+) ---------------
__device__ __forceinline__ uint32_t smem_u32(const void* p) {
    uint32_t a;
    asm("{ .reg .u64 t; cvta.to.shared.u64 t, %1; cvt.u32.u64 %0, t; }"
        : "=r"(a) : "l"(p));
    return a;
}
#define LDM_X4(r, addr)                                                        \
    asm volatile("ldmatrix.sync.aligned.m8n8.x4.shared.b16 {%0,%1,%2,%3}, [%4];" \
                 : "=r"((r)[0]), "=r"((r)[1]), "=r"((r)[2]), "=r"((r)[3])      \
                 : "r"(addr))
#define MMA_B16(c, a, b0, b1)                                                  \
    asm volatile("mma.sync.aligned.m16n8k16.row.col.f32.bf16.bf16.f32 "        \
                 "{%0,%1,%2,%3}, {%4,%5,%6,%7}, {%8,%9}, {%0,%1,%2,%3};"       \
                 : "+f"((c)[0]), "+f"((c)[1]), "+f"((c)[2]), "+f"((c)[3])      \
                 : "r"((a)[0]), "r"((a)[1]), "r"((a)[2]), "r"((a)[3]),         \
                   "r"(b0), "r"(b1))

// smem layout (bytes within dynamic smem); each tile 128 x KP bf16
#define T_BYTES (128 * KP * 2)          // 34816
#define SM_AH 0
#define SM_AL (SM_AH + T_BYTES)
#define SM_BH (SM_AL + T_BYTES)
#define SM_BL (SM_BH + T_BYTES)
#define SM_MMA_TOT (SM_BL + T_BYTES)    // 139264

__device__ __forceinline__ uint32_t pack_bf2(float a, float b) {
    __nv_bfloat162 h = __floats2bfloat162_rn(a, b);
    return *(uint32_t*)&h;
}

__device__ __forceinline__ void split_store(char* hb, char* lb, int row, int col,
                                            float v) {
    __nv_bfloat16 hi = __float2bfloat16(v);
    __nv_bfloat16 lo = __float2bfloat16(v - __bfloat162float(hi));
    int off = (row * KP + col) * 2;
    *(__nv_bfloat16*)(hb + off) = hi;
    *(__nv_bfloat16*)(lb + off) = lo;
}

// A-tile fill with packed 4B stores (hi/lo column pairs).
__device__ __forceinline__ void load_A(char* sm, const float* __restrict__ src,
                                       int r0, int tid) {
    for (int i = tid; i < 128 * 32; i += 256) {
        int r = i >> 5, c = (i & 31) * 4;
        int gr = r0 + r; if (gr >= N_NODES) gr = N_NODES - 1;
        float4 v = *(const float4*)(src + (size_t)gr * 128 + c);
        float h0 = __bfloat162float(__float2bfloat16(v.x));
        float h1 = __bfloat162float(__float2bfloat16(v.y));
        float h2 = __bfloat162float(__float2bfloat16(v.z));
        float h3 = __bfloat162float(__float2bfloat16(v.w));
        int off = (r * KP + c) * 2;
        *(uint32_t*)(sm + SM_AH + off)     = pack_bf2(v.x, v.y);
        *(uint32_t*)(sm + SM_AH + off + 4) = pack_bf2(v.z, v.w);
        *(uint32_t*)(sm + SM_AL + off)     = pack_bf2(v.x - h0, v.y - h1);
        *(uint32_t*)(sm + SM_AL + off + 4) = pack_bf2(v.z - h2, v.w - h3);
    }
}
// B tile as n-major (row n holds 128 k-values): W is k x n row-major.
__device__ __forceinline__ void load_B(char* sm, const float* __restrict__ W,
                                       int tid) {
    for (int i = tid; i < 128 * 32; i += 256) {
        int k = i >> 5, n0 = (i & 31) * 4;
        float4 v = *(const float4*)(W + k * 128 + n0);
        split_store(sm + SM_BH, sm + SM_BL, n0 + 0, k, v.x);
        split_store(sm + SM_BH, sm + SM_BL, n0 + 1, k, v.y);
        split_store(sm + SM_BH, sm + SM_BL, n0 + 2, k, v.z);
        split_store(sm + SM_BH, sm + SM_BL, n0 + 3, k, v.w);
    }
}

__device__ __forceinline__ void mma_sweep(uint32_t smb, int lane, int mB, int nB,
                                          float acc[2][8][4]) {
    int aRow = lane & 15;
    int aKH  = (lane >> 4) * 8;
    int bRow = (lane & 7) + ((lane >> 4) << 3);
    int bKH  = ((lane >> 3) & 1) * 8;
    #pragma unroll
    for (int ks = 0; ks < 8; ks++) {
        int k0 = ks * 16;
        uint32_t ah[2][4], al[2][4], bh[4][4], bl[4][4];
        #pragma unroll
        for (int mt = 0; mt < 2; mt++) {
            uint32_t off = (uint32_t)((mB + mt * 16 + aRow) * KP + k0 + aKH) * 2;
            LDM_X4(ah[mt], smb + SM_AH + off);
            LDM_X4(al[mt], smb + SM_AL + off);
        }
        #pragma unroll
        for (int p = 0; p < 4; p++) {
            uint32_t off = (uint32_t)((nB + p * 16 + bRow) * KP + k0 + bKH) * 2;
            LDM_X4(bh[p], smb + SM_BH + off);
            LDM_X4(bl[p], smb + SM_BL + off);
        }
        #pragma unroll
        for (int mt = 0; mt < 2; mt++)
            #pragma unroll
            for (int nt = 0; nt < 8; nt++) {
                int p = nt >> 1, q = (nt & 1) * 2;
                MMA_B16(acc[mt][nt], ah[mt], bh[p][q], bh[p][q + 1]);
                MMA_B16(acc[mt][nt], ah[mt], bl[p][q], bl[p][q + 1]);
                MMA_B16(acc[mt][nt], al[mt], bh[p][q], bh[p][q + 1]);
            }
    }
}

// ---------------- fused QKV GEMM: A tile staged once, loop over 3 W ---------
__global__ __launch_bounds__(256) void k_qkv_mma(const float* __restrict__ x,
                                                 const float* __restrict__ Wq,
                                                 const float* __restrict__ Wk,
                                                 const float* __restrict__ Wv) {
    extern __shared__ char sm[];
    int tid = threadIdx.x, lane = tid & 31, w = tid >> 5;
    int mB = (w >> 1) * 32, nB = (w & 1) * 64;
    int r0 = blockIdx.x * 128;
    uint32_t smb = smem_u32(sm);

    load_A(sm, x, r0, tid);

    int gq = lane >> 2, tq = lane & 3;
    #pragma unroll
    for (int m = 0; m < 3; m++) {
        const float* W = (m == 0) ? Wq : (m == 1) ? Wk : Wv;
        float* out = (m == 0) ? g_Q : (m == 1) ? g_K : g_V;
        __syncthreads();            // A ready (m=0) / previous sweep done
        load_B(sm, W, tid);
        __syncthreads();

        float acc[2][8][4];
        #pragma unroll
        for (int mt = 0; mt < 2; mt++)
            #pragma unroll
            for (int nt = 0; nt < 8; nt++)
                #pragma unroll
                for (int i = 0; i < 4; i++) acc[mt][nt][i] = 0.f;

        mma_sweep(smb, lane, mB, nB, acc);

        #pragma unroll
        for (int mt = 0; mt < 2; mt++)
            #pragma unroll
            for (int nt = 0; nt < 8; nt++) {
                int col = nB + nt * 8 + tq * 2;
                int row0 = r0 + mB + mt * 16 + gq;
                if (row0 < N_NODES)
                    *(float2*)(out + (size_t)row0 * 128 + col) =
                        make_float2(acc[mt][nt][0], acc[mt][nt][1]);
                int row1 = row0 + 8;
                if (row1 < N_NODES)
                    *(float2*)(out + (size_t)row1 * 128 + col) =
                        make_float2(acc[mt][nt][2], acc[mt][nt][3]);
            }
    }
}

// ---------------- output GEMM on mma.sync: relu(x@Wm_x + agg@Wf + bf) --------
__global__ __launch_bounds__(256) void k_out_mma(const float* __restrict__ x,
                                                 const float* __restrict__ Wm,
                                                 float* __restrict__ out) {
    extern __shared__ char sm[];
    int tid = threadIdx.x, lane = tid & 31, w = tid >> 5;
    int mB = (w >> 1) * 32, nB = (w & 1) * 64;
    int r0 = blockIdx.x * 128;
    uint32_t smb = smem_u32(sm);

    float acc[2][8][4];
    #pragma unroll
    for (int mt = 0; mt < 2; mt++)
        #pragma unroll
        for (int nt = 0; nt < 8; nt++)
            #pragma unroll
            for (int i = 0; i < 4; i++) acc[mt][nt][i] = 0.f;

    #pragma unroll
    for (int pass = 0; pass < 2; pass++) {
        const float* A = pass ? (const float*)g_agg : x;
        const float* B = pass ? (const float*)g_Wf : Wm;
        __syncthreads();
        load_A(sm, A, r0, tid);
        load_B(sm, B, tid);
        __syncthreads();
        mma_sweep(smb, lane, mB, nB, acc);
    }

    int gq = lane >> 2, tq = lane & 3;
    #pragma unroll
    for (int mt = 0; mt < 2; mt++)
        #pragma unroll
        for (int nt = 0; nt < 8; nt++) {
            int col = nB + nt * 8 + tq * 2;
            float b0 = g_bf[col], b1 = g_bf[col + 1];
            int row0 = r0 + mB + mt * 16 + gq;
            if (row0 < N_NODES)
                *(float2*)(out + (size_t)row0 * 128 + col) =
                    make_float2(fmaxf(acc[mt][nt][0] + b0, 0.f),
                                fmaxf(acc[mt][nt][1] + b1, 0.f));
            int row1 = row0 + 8;
            if (row1 < N_NODES)
                *(float2*)(out + (size_t)row1 * 128 + col) =
                    make_float2(fmaxf(acc[mt][nt][2] + b0, 0.f),
                                fmaxf(acc[mt][nt][3] + b1, 0.f));
        }
}

// ---------------- init / hist / scan / bucket / fusew ------------------------
__global__ void k_init() {
    int i = blockIdx.x * 256 + threadIdx.x;
    if (i < N_NODES) g_cnt[i] = 0;
}

__global__ __launch_bounds__(256) void k_hist(const int* __restrict__ ei) {
    int e = blockIdx.x * 256 + threadIdx.x;
    if (e >= N_EDGES) return;
    atomicAdd(&g_cnt[ei[N_EDGES + e]], 1);
}

__global__ void k_fusew(const float* __restrict__ Wo, const float* __restrict__ Wm,
                        const float* __restrict__ bo, const float* __restrict__ bm) {
    int r = blockIdx.x, j = threadIdx.x;
    float acc = 0.f;
    #pragma unroll 8
    for (int k = 0; k < 128; k++)
        acc += Wo[r * 128 + k] * Wm[(128 + k) * 128 + j];
    g_Wf[r * 128 + j] = acc;
    if (r == 0) {
        float b = bm[j];
        #pragma unroll 8
        for (int k = 0; k < 128; k++)
            b += bo[k] * Wm[(128 + k) * 128 + j];
        g_bf[j] = b;
    }
}

__global__ __launch_bounds__(SCAN_T) void k_scan() {
    __shared__ int sh[SCAN_T];
    int t = threadIdx.x;
    const int CHUNK = (N_NODES + SCAN_T - 1) / SCAN_T;
    int beg = t * CHUNK;
    int end = beg + CHUNK < N_NODES ? beg + CHUNK : N_NODES;
    int s = 0;
    for (int i = beg; i < end; i++) s += g_cnt[i];
    sh[t] = s;
    __syncthreads();
    for (int o = 1; o < SCAN_T; o <<= 1) {
        int v = (t >= o) ? sh[t - o] : 0;
        __syncthreads();
        sh[t] += v;
        __syncthreads();
    }
    int run = (t > 0) ? sh[t - 1] : 0;
    for (int i = beg; i < end; i++) {
        int c = g_cnt[i];
        g_off[i] = run;
        g_pos[i] = run;
        run += c;
    }
    if (beg < N_NODES && end == N_NODES) g_off[N_NODES] = run;
}

__global__ __launch_bounds__(256) void k_bucket(const int* __restrict__ ei,
                                                const float* __restrict__ ea,
                                                const float* __restrict__ We) {
    int e = blockIdx.x * 256 + threadIdx.x;
    if (e >= N_EDGES) return;
    int src = ei[e];
    int dst = ei[N_EDGES + e];
    float a0 = ea[e * 3 + 0], a1 = ea[e * 3 + 1], a2 = ea[e * 3 + 2];
    float4 b;
    b.x = a0 * We[0] + a1 * We[4] + a2 * We[8];
    b.y = a0 * We[1] + a1 * We[5] + a2 * We[9];
    b.z = a0 * We[2] + a1 * We[6] + a2 * We[10];
    b.w = a0 * We[3] + a1 * We[7] + a2 * We[11];
    int p = atomicAdd(&g_pos[dst], 1);
    g_src[p] = src;
    ((float4*)g_biasS)[p] = b;
}

// ---------------- fused attention + gather: warp/node, 4-edge pipeline -------
__global__ __launch_bounds__(256) void k_gather() {
    int n = blockIdx.x * 8 + (threadIdx.x >> 5);
    if (n >= N_NODES) return;
    int lane = threadIdx.x & 31;
    int h = lane >> 3;
    int beg = g_off[n];
    int end = g_off[n + 1];

    float4 q = ((const float4*)(g_Q + (size_t)n * 128))[lane];
    float4 acc = make_float4(0.f, 0.f, 0.f, 0.f);
    float s = 0.f;

    int i = beg;
    for (; i + 4 <= end; i += 4) {
        int   srcq[4];
        float biasq[4];
        #pragma unroll
        for (int j = 0; j < 4; j++) {
            srcq[j]  = g_src[i + j];
            biasq[j] = g_biasS[(i + j) * 4 + h];
        }
        float4 kq[4], vq[4];
        #pragma unroll
        for (int j = 0; j < 4; j++) {
            kq[j] = ((const float4*)(g_K + (size_t)srcq[j] * 128))[lane];
            vq[j] = ((const float4*)(g_V + (size_t)srcq[j] * 128))[lane];
        }
        float p[4];
        #pragma unroll
        for (int j = 0; j < 4; j++)
            p[j] = q.x * kq[j].x + q.y * kq[j].y + q.z * kq[j].z + q.w * kq[j].w;
        #pragma unroll
        for (int j = 0; j < 4; j++) p[j] += __shfl_xor_sync(0xffffffffu, p[j], 1);
        #pragma unroll
        for (int j = 0; j < 4; j++) p[j] += __shfl_xor_sync(0xffffffffu, p[j], 2);
        #pragma unroll
        for (int j = 0; j < 4; j++) p[j] += __shfl_xor_sync(0xffffffffu, p[j], 4);
        #pragma unroll
        for (int j = 0; j < 4; j++) {
            float a = p[j] * HD_SCALE + biasq[j];
            a = a >= 0.f ? a : 0.2f * a;
            float ex = __expf(a);
            s += ex;
            acc.x = fmaf(vq[j].x, ex, acc.x);
            acc.y = fmaf(vq[j].y, ex, acc.y);
            acc.z = fmaf(vq[j].z, ex, acc.z);
            acc.w = fmaf(vq[j].w, ex, acc.w);
        }
    }
    for (; i < end; i++) {
        int src = g_src[i];
        float bias = g_biasS[i * 4 + h];
        float4 k = ((const float4*)(g_K + (size_t)src * 128))[lane];
        float4 v = ((const float4*)(g_V + (size_t)src * 128))[lane];
        float p = q.x * k.x + q.y * k.y + q.z * k.z + q.w * k.w;
        p += __shfl_xor_sync(0xffffffffu, p, 1);
        p += __shfl_xor_sync(0xffffffffu, p, 2);
        p += __shfl_xor_sync(0xffffffffu, p, 4);
        float a = p * HD_SCALE + bias;
        a = a >= 0.f ? a : 0.2f * a;
        float ex = __expf(a);
        s += ex;
        acc.x = fmaf(v.x, ex, acc.x);
        acc.y = fmaf(v.y, ex, acc.y);
        acc.z = fmaf(v.z, ex, acc.z);
        acc.w = fmaf(v.w, ex, acc.w);
    }

    float inv = 1.f / fmaxf(s, 1e-12f);
    float4* o = (float4*)(g_agg + (size_t)n * 128);
    o[lane] = make_float4(acc.x * inv, acc.y * inv, acc.z * inv, acc.w * inv);
}

// ---------------- launch ------------------------------------------------------
extern "C" void kernel_launch(void* const* d_in, const int* in_sizes, int n_in,
                              void* d_out, int out_size) {
    const float* x  = (const float*)d_in[0];
    const int*   ei = (const int*)d_in[1];
    const float* ea = (const float*)d_in[2];
    const float* Wq = (const float*)d_in[3];
    const float* Wk = (const float*)d_in[4];
    const float* Wv = (const float*)d_in[5];
    const float* We = (const float*)d_in[6];
    const float* Wo = (const float*)d_in[7];
    const float* bo = (const float*)d_in[8];
    const float* Wm = (const float*)d_in[9];
    const float* bm = (const float*)d_in[10];
    float* out = (float*)d_out;

    static bool attr_done = false;
    if (!attr_done) {
        cudaFuncSetAttribute(k_qkv_mma, cudaFuncAttributeMaxDynamicSharedMemorySize,
                             SM_MMA_TOT);
        cudaFuncSetAttribute(k_out_mma, cudaFuncAttributeMaxDynamicSharedMemorySize,
                             SM_MMA_TOT);
        attr_done = true;
    }

    k_init<<<(N_NODES + 255) / 256, 256>>>();
    k_hist<<<(N_EDGES + 255) / 256, 256>>>(ei);
    k_scan<<<1, SCAN_T>>>();
    k_bucket<<<(N_EDGES + 255) / 256, 256>>>(ei, ea, We);
    k_fusew<<<128, 128>>>(Wo, Wm, bo, bm);
    k_qkv_mma<<<(N_NODES + 127) / 128, 256, SM_MMA_TOT>>>(x, Wq, Wk, Wv);
    k_gather<<<(N_NODES + 7) / 8, 256>>>();
    k_out_mma<<<(N_NODES + 127) / 128, 256, SM_MMA_TOT>>>(x, Wm, out);
}

// round 11
// speedup vs baseline: 1.7442x; 1.1279x over previous
#include <cuda_runtime.h>
#include <cuda_bf16.h>
#include <cstdint>

#define N_NODES 50000
#define N_EDGES 800000
#define HD_SCALE 0.17677669529663687f   // 1/sqrt(32)
#define SCAN_T 1024
#define KP 136                           // padded bf16 row stride (272B)

// ---------------- scratch (device globals: no allocation allowed) ----------
__device__ __align__(256) float g_Q[N_NODES * 128];
__device__ __align__(256) float g_K[N_NODES * 128];
__device__ __align__(256) float g_V[N_NODES * 128];
__device__ __align__(256) float g_biasS[N_EDGES * 4];
__device__ __align__(256) float g_agg[N_NODES * 128];
__device__ __align__(256) float g_Wf[128 * 128];
__device__ __align__(256) float g_bf[128];
__device__ __align__(256) int   g_cnt[N_NODES];
__device__ __align__(256) int   g_off[N_NODES + 1];
__device__ __align__(256) int   g_pos[N_NODES];
__device__ __align__(256) int   g_src[N_EDGES];

// ---------------- mma.sync helpers (arch-neutral PTX, sm_80+) ---------------
__device__ __forceinline__ uint32_t smem_u32(const void* p) {
    uint32_t a;
    asm("{ .reg .u64 t; cvta.to.shared.u64 t, %1; cvt.u32.u64 %0, t; }"
        : "=r"(a) : "l"(p));
    return a;
}
#define LDM_X4(r, addr)                                                        \
    asm volatile("ldmatrix.sync.aligned.m8n8.x4.shared.b16 {%0,%1,%2,%3}, [%4];" \
                 : "=r"((r)[0]), "=r"((r)[1]), "=r"((r)[2]), "=r"((r)[3])      \
                 : "r"(addr))
#define MMA_B16(c, a, b0, b1)                                                  \
    asm volatile("mma.sync.aligned.m16n8k16.row.col.f32.bf16.bf16.f32 "        \
                 "{%0,%1,%2,%3}, {%4,%5,%6,%7}, {%8,%9}, {%0,%1,%2,%3};"       \
                 : "+f"((c)[0]), "+f"((c)[1]), "+f"((c)[2]), "+f"((c)[3])      \
                 : "r"((a)[0]), "r"((a)[1]), "r"((a)[2]), "r"((a)[3]),         \
                   "r"(b0), "r"(b1))

// smem layout (bytes within dynamic smem); each tile 128 x KP bf16
#define T_BYTES (128 * KP * 2)          // 34816
#define SM_AH 0
#define SM_AL (SM_AH + T_BYTES)
#define SM_BH (SM_AL + T_BYTES)
#define SM_BL (SM_BH + T_BYTES)
#define SM_MMA_TOT (SM_BL + T_BYTES)    // 139264

__device__ __forceinline__ uint32_t pack_bf2(float a, float b) {
    __nv_bfloat162 h = __floats2bfloat162_rn(a, b);
    return *(uint32_t*)&h;
}

__device__ __forceinline__ void split_store(char* hb, char* lb, int row, int col,
                                            float v) {
    __nv_bfloat16 hi = __float2bfloat16(v);
    __nv_bfloat16 lo = __float2bfloat16(v - __bfloat162float(hi));
    int off = (row * KP + col) * 2;
    *(__nv_bfloat16*)(hb + off) = hi;
    *(__nv_bfloat16*)(lb + off) = lo;
}

__device__ __forceinline__ void load_A(char* sm, const float* __restrict__ src,
                                       int r0, int tid) {
    for (int i = tid; i < 128 * 32; i += 256) {
        int r = i >> 5, c = (i & 31) * 4;
        int gr = r0 + r; if (gr >= N_NODES) gr = N_NODES - 1;
        float4 v = *(const float4*)(src + (size_t)gr * 128 + c);
        float h0 = __bfloat162float(__float2bfloat16(v.x));
        float h1 = __bfloat162float(__float2bfloat16(v.y));
        float h2 = __bfloat162float(__float2bfloat16(v.z));
        float h3 = __bfloat162float(__float2bfloat16(v.w));
        int off = (r * KP + c) * 2;
        *(uint32_t*)(sm + SM_AH + off)     = pack_bf2(v.x, v.y);
        *(uint32_t*)(sm + SM_AH + off + 4) = pack_bf2(v.z, v.w);
        *(uint32_t*)(sm + SM_AL + off)     = pack_bf2(v.x - h0, v.y - h1);
        *(uint32_t*)(sm + SM_AL + off + 4) = pack_bf2(v.z - h2, v.w - h3);
    }
}
__device__ __forceinline__ void load_B(char* sm, const float* __restrict__ W,
                                       int tid) {
    for (int i = tid; i < 128 * 32; i += 256) {
        int k = i >> 5, n0 = (i & 31) * 4;
        float4 v = *(const float4*)(W + k * 128 + n0);
        split_store(sm + SM_BH, sm + SM_BL, n0 + 0, k, v.x);
        split_store(sm + SM_BH, sm + SM_BL, n0 + 1, k, v.y);
        split_store(sm + SM_BH, sm + SM_BL, n0 + 2, k, v.z);
        split_store(sm + SM_BH, sm + SM_BL, n0 + 3, k, v.w);
    }
}

__device__ __forceinline__ void mma_sweep(uint32_t smb, int lane, int mB, int nB,
                                          float acc[2][8][4]) {
    int aRow = lane & 15;
    int aKH  = (lane >> 4) * 8;
    int bRow = (lane & 7) + ((lane >> 4) << 3);
    int bKH  = ((lane >> 3) & 1) * 8;
    #pragma unroll
    for (int ks = 0; ks < 8; ks++) {
        int k0 = ks * 16;
        uint32_t ah[2][4], al[2][4], bh[4][4], bl[4][4];
        #pragma unroll
        for (int mt = 0; mt < 2; mt++) {
            uint32_t off = (uint32_t)((mB + mt * 16 + aRow) * KP + k0 + aKH) * 2;
            LDM_X4(ah[mt], smb + SM_AH + off);
            LDM_X4(al[mt], smb + SM_AL + off);
        }
        #pragma unroll
        for (int p = 0; p < 4; p++) {
            uint32_t off = (uint32_t)((nB + p * 16 + bRow) * KP + k0 + bKH) * 2;
            LDM_X4(bh[p], smb + SM_BH + off);
            LDM_X4(bl[p], smb + SM_BL + off);
        }
        #pragma unroll
        for (int mt = 0; mt < 2; mt++)
            #pragma unroll
            for (int nt = 0; nt < 8; nt++) {
                int p = nt >> 1, q = (nt & 1) * 2;
                MMA_B16(acc[mt][nt], ah[mt], bh[p][q], bh[p][q + 1]);
                MMA_B16(acc[mt][nt], ah[mt], bl[p][q], bl[p][q + 1]);
                MMA_B16(acc[mt][nt], al[mt], bh[p][q], bh[p][q + 1]);
            }
    }
}

// ---------------- fused QKV GEMM: A tile staged once, loop over 3 W ---------
__global__ __launch_bounds__(256) void k_qkv_mma(const float* __restrict__ x,
                                                 const float* __restrict__ Wq,
                                                 const float* __restrict__ Wk,
                                                 const float* __restrict__ Wv) {
    extern __shared__ char sm[];
    int tid = threadIdx.x, lane = tid & 31, w = tid >> 5;
    int mB = (w >> 1) * 32, nB = (w & 1) * 64;
    int r0 = blockIdx.x * 128;
    uint32_t smb = smem_u32(sm);

    load_A(sm, x, r0, tid);

    int gq = lane >> 2, tq = lane & 3;
    #pragma unroll
    for (int m = 0; m < 3; m++) {
        const float* W = (m == 0) ? Wq : (m == 1) ? Wk : Wv;
        float* out = (m == 0) ? g_Q : (m == 1) ? g_K : g_V;
        __syncthreads();
        load_B(sm, W, tid);
        __syncthreads();

        float acc[2][8][4];
        #pragma unroll
        for (int mt = 0; mt < 2; mt++)
            #pragma unroll
            for (int nt = 0; nt < 8; nt++)
                #pragma unroll
                for (int i = 0; i < 4; i++) acc[mt][nt][i] = 0.f;

        mma_sweep(smb, lane, mB, nB, acc);

        #pragma unroll
        for (int mt = 0; mt < 2; mt++)
            #pragma unroll
            for (int nt = 0; nt < 8; nt++) {
                int col = nB + nt * 8 + tq * 2;
                int row0 = r0 + mB + mt * 16 + gq;
                if (row0 < N_NODES)
                    *(float2*)(out + (size_t)row0 * 128 + col) =
                        make_float2(acc[mt][nt][0], acc[mt][nt][1]);
                int row1 = row0 + 8;
                if (row1 < N_NODES)
                    *(float2*)(out + (size_t)row1 * 128 + col) =
                        make_float2(acc[mt][nt][2], acc[mt][nt][3]);
            }
    }
}

// ---------------- output GEMM on mma.sync: relu(x@Wm_x + agg@Wf + bf) --------
__global__ __launch_bounds__(256) void k_out_mma(const float* __restrict__ x,
                                                 const float* __restrict__ Wm,
                                                 float* __restrict__ out) {
    extern __shared__ char sm[];
    int tid = threadIdx.x, lane = tid & 31, w = tid >> 5;
    int mB = (w >> 1) * 32, nB = (w & 1) * 64;
    int r0 = blockIdx.x * 128;
    uint32_t smb = smem_u32(sm);

    float acc[2][8][4];
    #pragma unroll
    for (int mt = 0; mt < 2; mt++)
        #pragma unroll
        for (int nt = 0; nt < 8; nt++)
            #pragma unroll
            for (int i = 0; i < 4; i++) acc[mt][nt][i] = 0.f;

    #pragma unroll
    for (int pass = 0; pass < 2; pass++) {
        const float* A = pass ? (const float*)g_agg : x;
        const float* B = pass ? (const float*)g_Wf : Wm;
        __syncthreads();
        load_A(sm, A, r0, tid);
        load_B(sm, B, tid);
        __syncthreads();
        mma_sweep(smb, lane, mB, nB, acc);
    }

    int gq = lane >> 2, tq = lane & 3;
    #pragma unroll
    for (int mt = 0; mt < 2; mt++)
        #pragma unroll
        for (int nt = 0; nt < 8; nt++) {
            int col = nB + nt * 8 + tq * 2;
            float b0 = g_bf[col], b1 = g_bf[col + 1];
            int row0 = r0 + mB + mt * 16 + gq;
            if (row0 < N_NODES)
                *(float2*)(out + (size_t)row0 * 128 + col) =
                    make_float2(fmaxf(acc[mt][nt][0] + b0, 0.f),
                                fmaxf(acc[mt][nt][1] + b1, 0.f));
            int row1 = row0 + 8;
            if (row1 < N_NODES)
                *(float2*)(out + (size_t)row1 * 128 + col) =
                    make_float2(fmaxf(acc[mt][nt][2] + b0, 0.f),
                                fmaxf(acc[mt][nt][3] + b1, 0.f));
        }
}

// ---------------- init / hist / scan / bucket / fusew ------------------------
__global__ void k_init() {
    int i = blockIdx.x * 256 + threadIdx.x;
    if (i < N_NODES) g_cnt[i] = 0;
}

__global__ __launch_bounds__(256) void k_hist(const int* __restrict__ ei) {
    int e = blockIdx.x * 256 + threadIdx.x;
    if (e >= N_EDGES) return;
    atomicAdd(&g_cnt[ei[N_EDGES + e]], 1);
}

__global__ void k_fusew(const float* __restrict__ Wo, const float* __restrict__ Wm,
                        const float* __restrict__ bo, const float* __restrict__ bm) {
    int r = blockIdx.x, j = threadIdx.x;
    float acc = 0.f;
    #pragma unroll 8
    for (int k = 0; k < 128; k++)
        acc += Wo[r * 128 + k] * Wm[(128 + k) * 128 + j];
    g_Wf[r * 128 + j] = acc;
    if (r == 0) {
        float b = bm[j];
        #pragma unroll 8
        for (int k = 0; k < 128; k++)
            b += bo[k] * Wm[(128 + k) * 128 + j];
        g_bf[j] = b;
    }
}

__global__ __launch_bounds__(SCAN_T) void k_scan() {
    __shared__ int sh[SCAN_T];
    int t = threadIdx.x;
    const int CHUNK = (N_NODES + SCAN_T - 1) / SCAN_T;
    int beg = t * CHUNK;
    int end = beg + CHUNK < N_NODES ? beg + CHUNK : N_NODES;
    int s = 0;
    for (int i = beg; i < end; i++) s += g_cnt[i];
    sh[t] = s;
    __syncthreads();
    for (int o = 1; o < SCAN_T; o <<= 1) {
        int v = (t >= o) ? sh[t - o] : 0;
        __syncthreads();
        sh[t] += v;
        __syncthreads();
    }
    int run = (t > 0) ? sh[t - 1] : 0;
    for (int i = beg; i < end; i++) {
        int c = g_cnt[i];
        g_off[i] = run;
        g_pos[i] = run;
        run += c;
    }
    if (beg < N_NODES && end == N_NODES) g_off[N_NODES] = run;
}

__global__ __launch_bounds__(256) void k_bucket(const int* __restrict__ ei,
                                                const float* __restrict__ ea,
                                                const float* __restrict__ We) {
    int e = blockIdx.x * 256 + threadIdx.x;
    if (e >= N_EDGES) return;
    int src = ei[e];
    int dst = ei[N_EDGES + e];
    float a0 = ea[e * 3 + 0], a1 = ea[e * 3 + 1], a2 = ea[e * 3 + 2];
    float4 b;
    b.x = a0 * We[0] + a1 * We[4] + a2 * We[8];
    b.y = a0 * We[1] + a1 * We[5] + a2 * We[9];
    b.z = a0 * We[2] + a1 * We[6] + a2 * We[10];
    b.w = a0 * We[3] + a1 * We[7] + a2 * We[11];
    int p = atomicAdd(&g_pos[dst], 1);
    g_src[p] = src;
    ((float4*)g_biasS)[p] = b;
}

// ---------------- fused attention + gather: warp/node, 4-edge pipeline -------
__global__ __launch_bounds__(256) void k_gather() {
    int n = blockIdx.x * 8 + (threadIdx.x >> 5);
    if (n >= N_NODES) return;
    int lane = threadIdx.x & 31;
    int h = lane >> 3;
    int beg = g_off[n];
    int end = g_off[n + 1];

    float4 q = ((const float4*)(g_Q + (size_t)n * 128))[lane];
    float4 acc = make_float4(0.f, 0.f, 0.f, 0.f);
    float s = 0.f;

    int i = beg;
    for (; i + 4 <= end; i += 4) {
        int   srcq[4];
        float biasq[4];
        #pragma unroll
        for (int j = 0; j < 4; j++) {
            srcq[j]  = g_src[i + j];
            biasq[j] = g_biasS[(i + j) * 4 + h];
        }
        float4 kq[4], vq[4];
        #pragma unroll
        for (int j = 0; j < 4; j++) {
            kq[j] = ((const float4*)(g_K + (size_t)srcq[j] * 128))[lane];
            vq[j] = ((const float4*)(g_V + (size_t)srcq[j] * 128))[lane];
        }
        float p[4];
        #pragma unroll
        for (int j = 0; j < 4; j++)
            p[j] = q.x * kq[j].x + q.y * kq[j].y + q.z * kq[j].z + q.w * kq[j].w;
        #pragma unroll
        for (int j = 0; j < 4; j++) p[j] += __shfl_xor_sync(0xffffffffu, p[j], 1);
        #pragma unroll
        for (int j = 0; j < 4; j++) p[j] += __shfl_xor_sync(0xffffffffu, p[j], 2);
        #pragma unroll
        for (int j = 0; j < 4; j++) p[j] += __shfl_xor_sync(0xffffffffu, p[j], 4);
        #pragma unroll
        for (int j = 0; j < 4; j++) {
            float a = p[j] * HD_SCALE + biasq[j];
            a = a >= 0.f ? a : 0.2f * a;
            float ex = __expf(a);
            s += ex;
            acc.x = fmaf(vq[j].x, ex, acc.x);
            acc.y = fmaf(vq[j].y, ex, acc.y);
            acc.z = fmaf(vq[j].z, ex, acc.z);
            acc.w = fmaf(vq[j].w, ex, acc.w);
        }
    }
    for (; i < end; i++) {
        int src = g_src[i];
        float bias = g_biasS[i * 4 + h];
        float4 k = ((const float4*)(g_K + (size_t)src * 128))[lane];
        float4 v = ((const float4*)(g_V + (size_t)src * 128))[lane];
        float p = q.x * k.x + q.y * k.y + q.z * k.z + q.w * k.w;
        p += __shfl_xor_sync(0xffffffffu, p, 1);
        p += __shfl_xor_sync(0xffffffffu, p, 2);
        p += __shfl_xor_sync(0xffffffffu, p, 4);
        float a = p * HD_SCALE + bias;
        a = a >= 0.f ? a : 0.2f * a;
        float ex = __expf(a);
        s += ex;
        acc.x = fmaf(v.x, ex, acc.x);
        acc.y = fmaf(v.y, ex, acc.y);
        acc.z = fmaf(v.z, ex, acc.z);
        acc.w = fmaf(v.w, ex, acc.w);
    }

    float inv = 1.f / fmaxf(s, 1e-12f);
    float4* o = (float4*)(g_agg + (size_t)n * 128);
    o[lane] = make_float4(acc.x * inv, acc.y * inv, acc.z * inv, acc.w * inv);
}

// ---------------- launch: fork CSR chain onto a side stream ------------------
extern "C" void kernel_launch(void* const* d_in, const int* in_sizes, int n_in,
                              void* d_out, int out_size) {
    const float* x  = (const float*)d_in[0];
    const int*   ei = (const int*)d_in[1];
    const float* ea = (const float*)d_in[2];
    const float* Wq = (const float*)d_in[3];
    const float* Wk = (const float*)d_in[4];
    const float* Wv = (const float*)d_in[5];
    const float* We = (const float*)d_in[6];
    const float* Wo = (const float*)d_in[7];
    const float* bo = (const float*)d_in[8];
    const float* Wm = (const float*)d_in[9];
    const float* bm = (const float*)d_in[10];
    float* out = (float*)d_out;

    static cudaStream_t s2 = nullptr;
    static cudaEvent_t evFork = nullptr, evJoin = nullptr;
    static bool init_done = false;
    if (!init_done) {
        cudaFuncSetAttribute(k_qkv_mma, cudaFuncAttributeMaxDynamicSharedMemorySize,
                             SM_MMA_TOT);
        cudaFuncSetAttribute(k_out_mma, cudaFuncAttributeMaxDynamicSharedMemorySize,
                             SM_MMA_TOT);
        cudaStreamCreateWithFlags(&s2, cudaStreamNonBlocking);
        cudaEventCreateWithFlags(&evFork, cudaEventDisableTiming);
        cudaEventCreateWithFlags(&evJoin, cudaEventDisableTiming);
        init_done = true;
    }

    // fork: CSR build chain + fusew run on s2, concurrent with QKV GEMM
    cudaEventRecord(evFork, 0);
    cudaStreamWaitEvent(s2, evFork, 0);

    k_init<<<(N_NODES + 255) / 256, 256, 0, s2>>>();
    k_hist<<<(N_EDGES + 255) / 256, 256, 0, s2>>>(ei);
    k_scan<<<1, SCAN_T, 0, s2>>>();
    k_bucket<<<(N_EDGES + 255) / 256, 256, 0, s2>>>(ei, ea, We);
    k_fusew<<<128, 128, 0, s2>>>(Wo, Wm, bo, bm);
    cudaEventRecord(evJoin, s2);

    // main stream: QKV GEMM (independent of CSR chain)
    k_qkv_mma<<<(N_NODES + 127) / 128, 256, SM_MMA_TOT>>>(x, Wq, Wk, Wv);

    // join: gather needs Q/K/V + CSR; out needs gather + fusew
    cudaStreamWaitEvent(0, evJoin, 0);
    k_gather<<<(N_NODES + 7) / 8, 256>>>();
    k_out_mma<<<(N_NODES + 127) / 128, 256, SM_MMA_TOT>>>(x, Wm, out);
}